// round 1
// baseline (speedup 1.0000x reference)
#include <cuda_runtime.h>
#include <math.h>

// Problem constants
#define BATCH 8
#define SEQ   1024
#define CDIM  768
#define NHEAD 12
#define HDIM  64
#define MTOT  (BATCH * SEQ)      // 8192
#define N_QKV (3 * CDIM)         // 2304

// Scratch (allocation-free rule: __device__ globals)
__device__ float g_q[BATCH * NHEAD * SEQ * HDIM];
__device__ float g_k[BATCH * NHEAD * SEQ * HDIM];
__device__ float g_v[BATCH * NHEAD * SEQ * HDIM];
__device__ float g_y[BATCH * SEQ * CDIM];

// ---------------------------------------------------------------------------
// Tiled SGEMM: C[M,N] = A[M,768] @ B[768,N] + bias
// BM=BN=128, BK=16, 256 threads, 8x8 micro-tile per thread.
// QKV=true: A = x, scatter epilogue into g_q/g_k/g_v with softmax scale folded
// QKV=false: A = g_y, plain epilogue into Cout
// ---------------------------------------------------------------------------
template <bool QKV>
__global__ __launch_bounds__(256)
void sgemm128(const float* __restrict__ Ain,
              const float* __restrict__ B,
              const float* __restrict__ bias,
              float* __restrict__ Cout,
              int N)
{
    const int K = CDIM;
    __shared__ float As[16][132];   // transposed A tile, padded
    __shared__ float Bs[16][128];

    const float* A = QKV ? Ain : (const float*)g_y;

    const int tid = threadIdx.x;
    const int m0 = blockIdx.y * 128;
    const int n0 = blockIdx.x * 128;
    const int tr = tid >> 4;        // 0..15
    const int tc = tid & 15;        // 0..15

    float acc[8][8];
#pragma unroll
    for (int i = 0; i < 8; i++)
#pragma unroll
        for (int j = 0; j < 8; j++) acc[i][j] = 0.f;

    for (int k0 = 0; k0 < K; k0 += 16) {
        // Load A tile (128 rows x 16 k), store transposed
#pragma unroll
        for (int it = 0; it < 2; it++) {
            int idx = tid + it * 256;          // 0..511 float4s
            int row = idx >> 2;                // 0..127
            int kq  = idx & 3;                 // 0..3
            float4 g = *(const float4*)(A + (m0 + row) * K + k0 + kq * 4);
            As[kq * 4 + 0][row] = g.x;
            As[kq * 4 + 1][row] = g.y;
            As[kq * 4 + 2][row] = g.z;
            As[kq * 4 + 3][row] = g.w;
        }
        // Load B tile (16 rows x 128 cols)
#pragma unroll
        for (int it = 0; it < 2; it++) {
            int idx = tid + it * 256;
            int row = idx >> 5;                // 0..15
            int nq  = idx & 31;                // 0..31
            *(float4*)(&Bs[row][nq * 4]) =
                *(const float4*)(B + (k0 + row) * N + n0 + nq * 4);
        }
        __syncthreads();

#pragma unroll
        for (int k = 0; k < 16; k++) {
            float areg[8], breg[8];
            *(float4*)(&areg[0]) = *(const float4*)(&As[k][tr * 8]);
            *(float4*)(&areg[4]) = *(const float4*)(&As[k][tr * 8 + 4]);
            *(float4*)(&breg[0]) = *(const float4*)(&Bs[k][tc * 8]);
            *(float4*)(&breg[4]) = *(const float4*)(&Bs[k][tc * 8 + 4]);
#pragma unroll
            for (int i = 0; i < 8; i++)
#pragma unroll
                for (int j = 0; j < 8; j++)
                    acc[i][j] = fmaf(areg[i], breg[j], acc[i][j]);
        }
        __syncthreads();
    }

    if (QKV) {
        // n0 is a multiple of 128 and 768%128==0 -> whole block in one of q/k/v
        const int which = n0 / CDIM;                  // 0=q 1=k 2=v (uniform)
        float* dst = (which == 0) ? g_q : (which == 1) ? g_k : g_v;
        const float scl = (which == 0) ? 0.125f : 1.0f;  // 1/sqrt(64) into Q
#pragma unroll
        for (int i = 0; i < 8; i++) {
            int m = m0 + tr * 8 + i;
            int b = m >> 10;
            int t = m & 1023;
#pragma unroll
            for (int j = 0; j < 8; j++) {
                int n = n0 + tc * 8 + j;
                int c = n - which * CDIM;
                int h = c >> 6;
                int d = c & 63;
                float val = (acc[i][j] + bias[n]) * scl;
                dst[(((b * NHEAD + h) * SEQ) + t) * HDIM + d] = val;
            }
        }
    } else {
#pragma unroll
        for (int i = 0; i < 8; i++) {
            int m = m0 + tr * 8 + i;
#pragma unroll
            for (int j = 0; j < 8; j++) {
                int n = n0 + tc * 8 + j;
                Cout[m * N + n] = acc[i][j] + bias[n];
            }
        }
    }
}

// ---------------------------------------------------------------------------
// Flash attention: one CTA per (batch*head, 64-query tile).
// 256 threads = 16x16 grid, each thread a 4x4 fragment.
// Online softmax; P staged through smem for the P@V GEMM.
// Scale 1/sqrt(64) already folded into Q by the QKV epilogue.
// ---------------------------------------------------------------------------
#define PCH 68                                     // padded smem pitch (floats)
#define ATTN_SMEM (4 * 64 * PCH * 4)               // Qs,Ks,Vs,Ps = 69632 B

__global__ __launch_bounds__(256)
void attn_kernel()
{
    extern __shared__ float sm[];
    float* Qs = sm;
    float* Ks = sm + 64 * PCH;
    float* Vs = sm + 2 * 64 * PCH;
    float* Ps = sm + 3 * 64 * PCH;

    const int bh = blockIdx.x;                     // 0..95
    const int qt = blockIdx.y;                     // 0..15
    const int q0 = qt * 64;
    const int tid = threadIdx.x;
    const int ty = tid >> 4;                       // 0..15 -> query rows ty*4..+4
    const int tx = tid & 15;                       // 0..15 -> cols tx*4..+4

    const float* qg = g_q + bh * SEQ * HDIM;
    const float* kg = g_k + bh * SEQ * HDIM;
    const float* vg = g_v + bh * SEQ * HDIM;

    // Load Q tile once
    for (int idx = tid; idx < 64 * 16; idx += 256) {
        int row = idx >> 4;
        int d4  = (idx & 15) * 4;
        *(float4*)(&Qs[row * PCH + d4]) =
            *(const float4*)(qg + (q0 + row) * HDIM + d4);
    }

    float m_i[4], l_i[4];
    float o[4][4];
#pragma unroll
    for (int i = 0; i < 4; i++) {
        m_i[i] = -1e30f; l_i[i] = 0.f;
#pragma unroll
        for (int j = 0; j < 4; j++) o[i][j] = 0.f;
    }

    const int ntiles = qt + 1;                     // causal: kv tiles 0..qt
    for (int kt = 0; kt < ntiles; kt++) {
        const int kv0 = kt * 64;
        __syncthreads();                           // protect Ks/Vs/Ps reuse
        for (int idx = tid; idx < 64 * 16; idx += 256) {
            int row = idx >> 4;
            int d4  = (idx & 15) * 4;
            *(float4*)(&Ks[row * PCH + d4]) =
                *(const float4*)(kg + (kv0 + row) * HDIM + d4);
            *(float4*)(&Vs[row * PCH + d4]) =
                *(const float4*)(vg + (kv0 + row) * HDIM + d4);
        }
        __syncthreads();

        // S = Q @ K^T  (64x64 tile, thread fragment 4x4)
        float s[4][4];
#pragma unroll
        for (int i = 0; i < 4; i++)
#pragma unroll
            for (int j = 0; j < 4; j++) s[i][j] = 0.f;

        for (int d = 0; d < HDIM; d += 4) {
            float4 qf[4], kf[4];
#pragma unroll
            for (int i = 0; i < 4; i++)
                qf[i] = *(const float4*)(&Qs[(ty * 4 + i) * PCH + d]);
#pragma unroll
            for (int j = 0; j < 4; j++)
                kf[j] = *(const float4*)(&Ks[(tx * 4 + j) * PCH + d]);
#pragma unroll
            for (int i = 0; i < 4; i++)
#pragma unroll
                for (int j = 0; j < 4; j++)
                    s[i][j] += qf[i].x * kf[j].x + qf[i].y * kf[j].y
                             + qf[i].z * kf[j].z + qf[i].w * kf[j].w;
        }

        // Causal mask: only the diagonal tile can contain masked entries
        if (kt == qt) {
#pragma unroll
            for (int i = 0; i < 4; i++)
#pragma unroll
                for (int j = 0; j < 4; j++)
                    if (kv0 + tx * 4 + j > q0 + ty * 4 + i) s[i][j] = -1e30f;
        }

        // Online softmax update per row (row group = 16 lanes, butterfly shfl)
#pragma unroll
        for (int i = 0; i < 4; i++) {
            float mx = fmaxf(fmaxf(s[i][0], s[i][1]), fmaxf(s[i][2], s[i][3]));
#pragma unroll
            for (int off = 8; off >= 1; off >>= 1)
                mx = fmaxf(mx, __shfl_xor_sync(0xffffffffu, mx, off));
            float mnew = fmaxf(m_i[i], mx);
            float alpha = __expf(m_i[i] - mnew);
            float rs = 0.f;
#pragma unroll
            for (int j = 0; j < 4; j++) {
                s[i][j] = __expf(s[i][j] - mnew);
                rs += s[i][j];
            }
#pragma unroll
            for (int off = 8; off >= 1; off >>= 1)
                rs += __shfl_xor_sync(0xffffffffu, rs, off);
            l_i[i] = l_i[i] * alpha + rs;
            m_i[i] = mnew;
#pragma unroll
            for (int j = 0; j < 4; j++) {
                o[i][j] *= alpha;
                Ps[(ty * 4 + i) * PCH + tx * 4 + j] = s[i][j];
            }
        }
        __syncthreads();

        // O += P @ V  (thread fragment: rows ty*4..+4, d-cols tx*4..+4)
        for (int kk = 0; kk < 64; kk += 4) {
            float4 pv[4], vv[4];
#pragma unroll
            for (int i = 0; i < 4; i++)
                pv[i] = *(const float4*)(&Ps[(ty * 4 + i) * PCH + kk]);
#pragma unroll
            for (int u = 0; u < 4; u++)
                vv[u] = *(const float4*)(&Vs[(kk + u) * PCH + tx * 4]);
#pragma unroll
            for (int i = 0; i < 4; i++) {
                float4 p4 = pv[i];
                o[i][0] = fmaf(p4.x, vv[0].x, o[i][0]);
                o[i][0] = fmaf(p4.y, vv[1].x, o[i][0]);
                o[i][0] = fmaf(p4.z, vv[2].x, o[i][0]);
                o[i][0] = fmaf(p4.w, vv[3].x, o[i][0]);
                o[i][1] = fmaf(p4.x, vv[0].y, o[i][1]);
                o[i][1] = fmaf(p4.y, vv[1].y, o[i][1]);
                o[i][1] = fmaf(p4.z, vv[2].y, o[i][1]);
                o[i][1] = fmaf(p4.w, vv[3].y, o[i][1]);
                o[i][2] = fmaf(p4.x, vv[0].z, o[i][2]);
                o[i][2] = fmaf(p4.y, vv[1].z, o[i][2]);
                o[i][2] = fmaf(p4.z, vv[2].z, o[i][2]);
                o[i][2] = fmaf(p4.w, vv[3].z, o[i][2]);
                o[i][3] = fmaf(p4.x, vv[0].w, o[i][3]);
                o[i][3] = fmaf(p4.y, vv[1].w, o[i][3]);
                o[i][3] = fmaf(p4.z, vv[2].w, o[i][3]);
                o[i][3] = fmaf(p4.w, vv[3].w, o[i][3]);
            }
        }
    }

    // Normalize and write y[b, t, h*64+d]
    const int h = bh % NHEAD;
    const int b = bh / NHEAD;
#pragma unroll
    for (int i = 0; i < 4; i++) {
        float inv = 1.f / l_i[i];
        int t = q0 + ty * 4 + i;
#pragma unroll
        for (int j = 0; j < 4; j++)
            g_y[(b * SEQ + t) * CDIM + h * HDIM + tx * 4 + j] = o[i][j] * inv;
    }
}

// ---------------------------------------------------------------------------
extern "C" void kernel_launch(void* const* d_in, const int* in_sizes, int n_in,
                              void* d_out, int out_size)
{
    const float* x  = (const float*)d_in[0];
    const float* Wa = (const float*)d_in[1];
    const float* ba = (const float*)d_in[2];
    const float* Wp = (const float*)d_in[3];
    const float* bp = (const float*)d_in[4];
    float* out = (float*)d_out;

    cudaFuncSetAttribute(attn_kernel,
                         cudaFuncAttributeMaxDynamicSharedMemorySize, ATTN_SMEM);

    // 1) QKV projection, scatter to [B, NH, T, HD] with bias + q-scale folded
    sgemm128<true><<<dim3(N_QKV / 128, MTOT / 128), 256>>>(x, Wa, ba, nullptr, N_QKV);

    // 2) Causal flash attention -> g_y [B, T, C]
    attn_kernel<<<dim3(BATCH * NHEAD, SEQ / 64), 256, ATTN_SMEM>>>();

    // 3) Output projection
    sgemm128<false><<<dim3(CDIM / 128, MTOT / 128), 256>>>(nullptr, Wp, bp, out, CDIM);
}

// round 4
// speedup vs baseline: 1.5642x; 1.5642x over previous
#include <cuda_runtime.h>
#include <cuda_bf16.h>
#include <cstdint>
#include <math.h>

// Problem constants
#define BATCH 8
#define SEQ   1024
#define CDIM  768
#define NHEAD 12
#define HDIM  64
#define MTOT  (BATCH * SEQ)      // 8192
#define N_QKV (3 * CDIM)         // 2304

// ---------------------------------------------------------------------------
// Scratch (allocation-free rule: __device__ globals)
// ---------------------------------------------------------------------------
__device__ float g_q[BATCH * NHEAD * SEQ * HDIM];
__device__ float g_k[BATCH * NHEAD * SEQ * HDIM];
__device__ float g_v[BATCH * NHEAD * SEQ * HDIM];
__device__ float g_y[BATCH * SEQ * CDIM];

// bf16 hi/lo split operands for the HMMA GEMMs
__device__ __nv_bfloat16 g_xh[MTOT * CDIM];
__device__ __nv_bfloat16 g_xl[MTOT * CDIM];
__device__ __nv_bfloat16 g_yh[MTOT * CDIM];
__device__ __nv_bfloat16 g_yl[MTOT * CDIM];
__device__ __nv_bfloat16 g_wah[N_QKV * CDIM];   // W_attn^T  [N=2304, K=768]
__device__ __nv_bfloat16 g_wal[N_QKV * CDIM];
__device__ __nv_bfloat16 g_wph[CDIM * CDIM];    // W_proj^T  [N=768,  K=768]
__device__ __nv_bfloat16 g_wpl[CDIM * CDIM];

// ---------------------------------------------------------------------------
// PTX helpers (arch-agnostic: valid on compute_103 / sm_103)
// ---------------------------------------------------------------------------
__device__ __forceinline__ uint32_t smem_u32(const void* p) {
    uint32_t a;
    asm("{ .reg .u64 t; cvta.to.shared.u64 t, %1; cvt.u32.u64 %0, t; }"
        : "=r"(a) : "l"(p));
    return a;
}

__device__ __forceinline__ void cp16(uint32_t saddr, const void* g) {
    asm volatile("cp.async.cg.shared.global [%0], [%1], 16;"
                 :: "r"(saddr), "l"(g) : "memory");
}

__device__ __forceinline__ void ldmx4(uint32_t* r, uint32_t addr) {
    asm volatile("ldmatrix.sync.aligned.m8n8.x4.shared.b16 {%0,%1,%2,%3}, [%4];"
                 : "=r"(r[0]), "=r"(r[1]), "=r"(r[2]), "=r"(r[3]) : "r"(addr));
}

__device__ __forceinline__ void mma_bf16(float* d, const uint32_t* a,
                                         const uint32_t* b) {
    asm volatile(
        "mma.sync.aligned.m16n8k16.row.col.f32.bf16.bf16.f32 "
        "{%0,%1,%2,%3}, {%4,%5,%6,%7}, {%8,%9}, {%0,%1,%2,%3};"
        : "+f"(d[0]), "+f"(d[1]), "+f"(d[2]), "+f"(d[3])
        : "r"(a[0]), "r"(a[1]), "r"(a[2]), "r"(a[3]), "r"(b[0]), "r"(b[1]));
}

// ---------------------------------------------------------------------------
// bf16 hi/lo split kernels
// ---------------------------------------------------------------------------
template <int WHICH>
__global__ void split_kernel(const float* __restrict__ in_param, int n) {
    const float* in = WHICH ? (const float*)g_y : in_param;
    __nv_bfloat16* hi = WHICH ? g_yh : g_xh;
    __nv_bfloat16* lo = WHICH ? g_yl : g_xl;
    int idx = (blockIdx.x * blockDim.x + threadIdx.x) * 4;
    if (idx >= n) return;
    float4 v = *(const float4*)(in + idx);
    __nv_bfloat16 h0 = __float2bfloat16(v.x);
    __nv_bfloat16 h1 = __float2bfloat16(v.y);
    __nv_bfloat16 h2 = __float2bfloat16(v.z);
    __nv_bfloat16 h3 = __float2bfloat16(v.w);
    __nv_bfloat16 l0 = __float2bfloat16(v.x - __bfloat162float(h0));
    __nv_bfloat16 l1 = __float2bfloat16(v.y - __bfloat162float(h1));
    __nv_bfloat16 l2 = __float2bfloat16(v.z - __bfloat162float(h2));
    __nv_bfloat16 l3 = __float2bfloat16(v.w - __bfloat162float(h3));
    __nv_bfloat162 a, b;
    a.x = h0; a.y = h1; b.x = h2; b.y = h3;
    *(__nv_bfloat162*)(hi + idx)     = a;
    *(__nv_bfloat162*)(hi + idx + 2) = b;
    a.x = l0; a.y = l1; b.x = l2; b.y = l3;
    *(__nv_bfloat162*)(lo + idx)     = a;
    *(__nv_bfloat162*)(lo + idx + 2) = b;
}

// Transpose + split: in [R, C] fp32 -> hi/lo [C, R] bf16
template <int WHICH>
__global__ void tsplit_kernel(const float* __restrict__ in, int R, int C) {
    __nv_bfloat16* hi = WHICH ? g_wph : g_wah;
    __nv_bfloat16* lo = WHICH ? g_wpl : g_wal;
    __shared__ float tile[32][33];
    int c0 = blockIdx.x * 32, r0 = blockIdx.y * 32;
    int tx = threadIdx.x, ty = threadIdx.y;
#pragma unroll
    for (int dy = 0; dy < 32; dy += 8)
        tile[ty + dy][tx] = in[(r0 + ty + dy) * C + c0 + tx];
    __syncthreads();
#pragma unroll
    for (int dy = 0; dy < 32; dy += 8) {
        int c = c0 + ty + dy, r = r0 + tx;
        float v = tile[tx][ty + dy];
        __nv_bfloat16 h = __float2bfloat16(v);
        __nv_bfloat16 l = __float2bfloat16(v - __bfloat162float(h));
        hi[(size_t)c * R + r] = h;
        lo[(size_t)c * R + r] = l;
    }
}

// ---------------------------------------------------------------------------
// HMMA GEMM: D[M,N] = A[M,768] @ B^T[N,768] (+bias), bf16 hi/lo split.
// CTA tile 128x128, BK=32, cp.async double-buffer, mma.sync m16n8k16.
// 8 warps = 4(m) x 2(n); warp tile 32x64 -> 2(mi) x 8(ni) mma tiles.
// MODE 1: scatter into g_q/g_k/g_v (bias + q-scale 0.125)
// MODE 0: bias epilogue into Cout
// ---------------------------------------------------------------------------
#define BK        32
#define ROWB      80                       // padded row: 32*2 + 16 bytes
#define TILE_B    (128 * ROWB)             // 10240 B per operand tile
#define STAGE_B   (4 * TILE_B)             // Ah, Al, Bh, Bl = 40960 B
#define GEMM_SMEM (2 * STAGE_B)            // 81920 B

template <int MODE>
__global__ __launch_bounds__(256)
void tc_gemm(const float* __restrict__ bias, float* __restrict__ Cout) {
    constexpr int N = MODE ? N_QKV : CDIM;
    constexpr int K = CDIM;
    constexpr int NCH = K / BK;            // 24

    const __nv_bfloat16* Ah = MODE ? g_xh : g_yh;
    const __nv_bfloat16* Al = MODE ? g_xl : g_yl;
    const __nv_bfloat16* Bh = MODE ? g_wah : g_wph;
    const __nv_bfloat16* Bl = MODE ? g_wal : g_wpl;

    extern __shared__ char smem[];
    const uint32_t sb = smem_u32(smem);

    const int tid  = threadIdx.x;
    const int lane = tid & 31;
    const int w    = tid >> 5;
    const int wm   = w & 3;                // 0..3  -> m offset wm*32
    const int wn   = w >> 2;               // 0..1  -> n offset wn*64
    const int m0   = blockIdx.y * 128;
    const int n0   = blockIdx.x * 128;

    float acc[2][8][4];
#pragma unroll
    for (int i = 0; i < 2; i++)
#pragma unroll
        for (int j = 0; j < 8; j++)
#pragma unroll
            for (int v = 0; v < 4; v++) acc[i][j][v] = 0.f;

    // --- async prefetch of chunk c into stage s ---
    auto prefetch = [&](int c, int s) {
        const int k0 = c * BK;
        const uint32_t stage = sb + (uint32_t)s * STAGE_B;
#pragma unroll
        for (int t = 0; t < 8; t++) {
            int idx  = tid + t * 256;          // 0..2047
            int tile = idx >> 9;               // 0..3
            int wi   = idx & 511;
            int r    = wi >> 2;                // 0..127
            int ch   = wi & 3;                 // 0..3 (16B chunks)
            uint32_t saddr = stage + (uint32_t)tile * TILE_B + r * ROWB + ch * 16;
            const __nv_bfloat16* src;
            if (tile == 0)      src = Ah + (size_t)(m0 + r) * K + k0 + ch * 8;
            else if (tile == 1) src = Al + (size_t)(m0 + r) * K + k0 + ch * 8;
            else if (tile == 2) src = Bh + (size_t)(n0 + r) * K + k0 + ch * 8;
            else                src = Bl + (size_t)(n0 + r) * K + k0 + ch * 8;
            cp16(saddr, src);
        }
        asm volatile("cp.async.commit_group;" ::: "memory");
    };

    prefetch(0, 0);
    prefetch(1, 1);

    // ldmatrix per-lane address offsets (within a tile)
    const uint32_t a_off =
        (uint32_t)(wm * 32 + (lane & 15)) * ROWB + ((lane >> 4) << 3) * 2;
    const uint32_t b_off =
        (uint32_t)(wn * 64 + (lane & 7) + ((lane >> 4) << 3)) * ROWB +
        (((lane >> 3) & 1) << 3) * 2;

    for (int c = 0; c < NCH; c++) {
        const int s = c & 1;
        if (c + 1 < NCH)
            asm volatile("cp.async.wait_group 1;" ::: "memory");
        else
            asm volatile("cp.async.wait_group 0;" ::: "memory");
        __syncthreads();

        const uint32_t stage = sb + (uint32_t)s * STAGE_B;
#pragma unroll
        for (int kk = 0; kk < BK; kk += 16) {
            uint32_t ah[2][4], al[2][4], bh[8][2], bl[8][2];
#pragma unroll
            for (int mi = 0; mi < 2; mi++) {
                uint32_t off = a_off + (uint32_t)(mi * 16) * ROWB + kk * 2;
                ldmx4(ah[mi], stage + off);
                ldmx4(al[mi], stage + TILE_B + off);
            }
#pragma unroll
            for (int np = 0; np < 4; np++) {
                uint32_t off = b_off + (uint32_t)(np * 16) * ROWB + kk * 2;
                uint32_t rh[4], rl[4];
                ldmx4(rh, stage + 2 * TILE_B + off);
                ldmx4(rl, stage + 3 * TILE_B + off);
                bh[2 * np][0] = rh[0]; bh[2 * np][1] = rh[1];
                bh[2 * np + 1][0] = rh[2]; bh[2 * np + 1][1] = rh[3];
                bl[2 * np][0] = rl[0]; bl[2 * np][1] = rl[1];
                bl[2 * np + 1][0] = rl[2]; bl[2 * np + 1][1] = rl[3];
            }
#pragma unroll
            for (int mi = 0; mi < 2; mi++)
#pragma unroll
                for (int ni = 0; ni < 8; ni++) {
                    mma_bf16(acc[mi][ni], ah[mi], bh[ni]);
                    mma_bf16(acc[mi][ni], ah[mi], bl[ni]);
                    mma_bf16(acc[mi][ni], al[mi], bh[ni]);
                }
        }
        __syncthreads();
        if (c + 2 < NCH) prefetch(c + 2, s);
    }

    // ---- epilogue ----
    const int mrow = m0 + wm * 32 + (lane >> 2);
    const int ncol = n0 + wn * 64 + 2 * (lane & 3);
#pragma unroll
    for (int mi = 0; mi < 2; mi++) {
#pragma unroll
        for (int ni = 0; ni < 8; ni++) {
            const int n = ncol + ni * 8;
            const float b0 = bias[n], b1 = bias[n + 1];
#pragma unroll
            for (int half = 0; half < 2; half++) {
                const int m = mrow + mi * 16 + half * 8;
                float v0 = acc[mi][ni][2 * half + 0] + b0;
                float v1 = acc[mi][ni][2 * half + 1] + b1;
                if (MODE == 1) {
                    const int which = n0 / CDIM;   // tile fully in q, k or v
                    const float scl = (which == 0) ? 0.125f : 1.0f;
                    float* dstb = (which == 0) ? g_q : (which == 1) ? g_k : g_v;
                    const int cloc = n - which * CDIM;
                    const int h = cloc >> 6;
                    const int d = cloc & 63;
                    const int bb = m >> 10, t = m & 1023;
                    float2 o; o.x = v0 * scl; o.y = v1 * scl;
                    *(float2*)(dstb +
                        (((size_t)(bb * NHEAD + h) * SEQ + t) * HDIM + d)) = o;
                } else {
                    float2 o; o.x = v0; o.y = v1;
                    *(float2*)(Cout + (size_t)m * N + n) = o;
                }
            }
        }
    }
}

// ---------------------------------------------------------------------------
// Flash attention (unchanged from the R1 passing kernel)
// ---------------------------------------------------------------------------
#define PCH 68
#define ATTN_SMEM (4 * 64 * PCH * 4)

__global__ __launch_bounds__(256)
void attn_kernel()
{
    extern __shared__ float sm[];
    float* Qs = sm;
    float* Ks = sm + 64 * PCH;
    float* Vs = sm + 2 * 64 * PCH;
    float* Ps = sm + 3 * 64 * PCH;

    const int bh = blockIdx.x;
    const int qt = blockIdx.y;
    const int q0 = qt * 64;
    const int tid = threadIdx.x;
    const int ty = tid >> 4;
    const int tx = tid & 15;

    const float* qg = g_q + bh * SEQ * HDIM;
    const float* kg = g_k + bh * SEQ * HDIM;
    const float* vg = g_v + bh * SEQ * HDIM;

    for (int idx = tid; idx < 64 * 16; idx += 256) {
        int row = idx >> 4;
        int d4  = (idx & 15) * 4;
        *(float4*)(&Qs[row * PCH + d4]) =
            *(const float4*)(qg + (q0 + row) * HDIM + d4);
    }

    float m_i[4], l_i[4];
    float o[4][4];
#pragma unroll
    for (int i = 0; i < 4; i++) {
        m_i[i] = -1e30f; l_i[i] = 0.f;
#pragma unroll
        for (int j = 0; j < 4; j++) o[i][j] = 0.f;
    }

    const int ntiles = qt + 1;
    for (int kt = 0; kt < ntiles; kt++) {
        const int kv0 = kt * 64;
        __syncthreads();
        for (int idx = tid; idx < 64 * 16; idx += 256) {
            int row = idx >> 4;
            int d4  = (idx & 15) * 4;
            *(float4*)(&Ks[row * PCH + d4]) =
                *(const float4*)(kg + (kv0 + row) * HDIM + d4);
            *(float4*)(&Vs[row * PCH + d4]) =
                *(const float4*)(vg + (kv0 + row) * HDIM + d4);
        }
        __syncthreads();

        float s[4][4];
#pragma unroll
        for (int i = 0; i < 4; i++)
#pragma unroll
            for (int j = 0; j < 4; j++) s[i][j] = 0.f;

        for (int d = 0; d < HDIM; d += 4) {
            float4 qf[4], kf[4];
#pragma unroll
            for (int i = 0; i < 4; i++)
                qf[i] = *(const float4*)(&Qs[(ty * 4 + i) * PCH + d]);
#pragma unroll
            for (int j = 0; j < 4; j++)
                kf[j] = *(const float4*)(&Ks[(tx * 4 + j) * PCH + d]);
#pragma unroll
            for (int i = 0; i < 4; i++)
#pragma unroll
                for (int j = 0; j < 4; j++)
                    s[i][j] += qf[i].x * kf[j].x + qf[i].y * kf[j].y
                             + qf[i].z * kf[j].z + qf[i].w * kf[j].w;
        }

        if (kt == qt) {
#pragma unroll
            for (int i = 0; i < 4; i++)
#pragma unroll
                for (int j = 0; j < 4; j++)
                    if (kv0 + tx * 4 + j > q0 + ty * 4 + i) s[i][j] = -1e30f;
        }

#pragma unroll
        for (int i = 0; i < 4; i++) {
            float mx = fmaxf(fmaxf(s[i][0], s[i][1]), fmaxf(s[i][2], s[i][3]));
#pragma unroll
            for (int off = 8; off >= 1; off >>= 1)
                mx = fmaxf(mx, __shfl_xor_sync(0xffffffffu, mx, off));
            float mnew = fmaxf(m_i[i], mx);
            float alpha = __expf(m_i[i] - mnew);
            float rs = 0.f;
#pragma unroll
            for (int j = 0; j < 4; j++) {
                s[i][j] = __expf(s[i][j] - mnew);
                rs += s[i][j];
            }
#pragma unroll
            for (int off = 8; off >= 1; off >>= 1)
                rs += __shfl_xor_sync(0xffffffffu, rs, off);
            l_i[i] = l_i[i] * alpha + rs;
            m_i[i] = mnew;
#pragma unroll
            for (int j = 0; j < 4; j++) {
                o[i][j] *= alpha;
                Ps[(ty * 4 + i) * PCH + tx * 4 + j] = s[i][j];
            }
        }
        __syncthreads();

        for (int kk = 0; kk < 64; kk += 4) {
            float4 pv[4], vv[4];
#pragma unroll
            for (int i = 0; i < 4; i++)
                pv[i] = *(const float4*)(&Ps[(ty * 4 + i) * PCH + kk]);
#pragma unroll
            for (int u = 0; u < 4; u++)
                vv[u] = *(const float4*)(&Vs[(kk + u) * PCH + tx * 4]);
#pragma unroll
            for (int i = 0; i < 4; i++) {
                float4 p4 = pv[i];
                o[i][0] = fmaf(p4.x, vv[0].x, o[i][0]);
                o[i][0] = fmaf(p4.y, vv[1].x, o[i][0]);
                o[i][0] = fmaf(p4.z, vv[2].x, o[i][0]);
                o[i][0] = fmaf(p4.w, vv[3].x, o[i][0]);
                o[i][1] = fmaf(p4.x, vv[0].y, o[i][1]);
                o[i][1] = fmaf(p4.y, vv[1].y, o[i][1]);
                o[i][1] = fmaf(p4.z, vv[2].y, o[i][1]);
                o[i][1] = fmaf(p4.w, vv[3].y, o[i][1]);
                o[i][2] = fmaf(p4.x, vv[0].z, o[i][2]);
                o[i][2] = fmaf(p4.y, vv[1].z, o[i][2]);
                o[i][2] = fmaf(p4.z, vv[2].z, o[i][2]);
                o[i][2] = fmaf(p4.w, vv[3].z, o[i][2]);
                o[i][3] = fmaf(p4.x, vv[0].w, o[i][3]);
                o[i][3] = fmaf(p4.y, vv[1].w, o[i][3]);
                o[i][3] = fmaf(p4.z, vv[2].w, o[i][3]);
                o[i][3] = fmaf(p4.w, vv[3].w, o[i][3]);
            }
        }
    }

    const int h = bh % NHEAD;
    const int b = bh / NHEAD;
#pragma unroll
    for (int i = 0; i < 4; i++) {
        float inv = 1.f / l_i[i];
        int t = q0 + ty * 4 + i;
#pragma unroll
        for (int j = 0; j < 4; j++)
            g_y[(b * SEQ + t) * CDIM + h * HDIM + tx * 4 + j] = o[i][j] * inv;
    }
}

// ---------------------------------------------------------------------------
extern "C" void kernel_launch(void* const* d_in, const int* in_sizes, int n_in,
                              void* d_out, int out_size)
{
    const float* x  = (const float*)d_in[0];
    const float* Wa = (const float*)d_in[1];
    const float* ba = (const float*)d_in[2];
    const float* Wp = (const float*)d_in[3];
    const float* bp = (const float*)d_in[4];
    float* out = (float*)d_out;

    cudaFuncSetAttribute(attn_kernel,
                         cudaFuncAttributeMaxDynamicSharedMemorySize, ATTN_SMEM);
    cudaFuncSetAttribute(tc_gemm<1>,
                         cudaFuncAttributeMaxDynamicSharedMemorySize, GEMM_SMEM);
    cudaFuncSetAttribute(tc_gemm<0>,
                         cudaFuncAttributeMaxDynamicSharedMemorySize, GEMM_SMEM);

    const int nx = MTOT * CDIM;                       // 6291456

    // 1) bf16 hi/lo splits of x and the (transposed) weights
    split_kernel<0><<<nx / 1024, 256>>>(x, nx);
    tsplit_kernel<0><<<dim3(N_QKV / 32, CDIM / 32), dim3(32, 8)>>>(Wa, CDIM, N_QKV);
    tsplit_kernel<1><<<dim3(CDIM / 32, CDIM / 32), dim3(32, 8)>>>(Wp, CDIM, CDIM);

    // 2) QKV projection on HMMA, scatter to [B,NH,T,HD] (+bias, q-scale)
    tc_gemm<1><<<dim3(N_QKV / 128, MTOT / 128), 256, GEMM_SMEM>>>(ba, nullptr);

    // 3) Causal flash attention -> g_y [B,T,C]
    attn_kernel<<<dim3(BATCH * NHEAD, SEQ / 64), 256, ATTN_SMEM>>>();

    // 4) Split y, then output projection on HMMA
    split_kernel<1><<<nx / 1024, 256>>>(nullptr, nx);
    tc_gemm<0><<<dim3(CDIM / 128, MTOT / 128), 256, GEMM_SMEM>>>(bp, out);
}

// round 11
// speedup vs baseline: 2.7634x; 1.7666x over previous
#include <cuda_runtime.h>
#include <cuda_bf16.h>
#include <cstdint>
#include <math.h>

// Problem constants
#define BATCH 8
#define SEQ   1024
#define CDIM  768
#define NHEAD 12
#define HDIM  64
#define MTOT  (BATCH * SEQ)      // 8192
#define N_QKV (3 * CDIM)         // 2304
#define NBH   (BATCH * NHEAD)    // 96

// ---------------------------------------------------------------------------
// Scratch (allocation-free rule: __device__ globals)
// ---------------------------------------------------------------------------
// bf16 hi/lo split operands
__device__ __nv_bfloat16 g_xh[MTOT * CDIM];
__device__ __nv_bfloat16 g_xl[MTOT * CDIM];
__device__ __nv_bfloat16 g_yh[MTOT * CDIM];
__device__ __nv_bfloat16 g_yl[MTOT * CDIM];
__device__ __nv_bfloat16 g_wah[N_QKV * CDIM];   // W_attn^T  [N=2304, K=768]
__device__ __nv_bfloat16 g_wal[N_QKV * CDIM];
__device__ __nv_bfloat16 g_wph[CDIM * CDIM];    // W_proj^T  [N=768,  K=768]
__device__ __nv_bfloat16 g_wpl[CDIM * CDIM];
// attention operands, bf16 hi/lo, per-head layouts
__device__ __nv_bfloat16 g_qh[NBH * SEQ * HDIM];   // [bh][t][d] (q pre-scaled)
__device__ __nv_bfloat16 g_ql[NBH * SEQ * HDIM];
__device__ __nv_bfloat16 g_kh[NBH * SEQ * HDIM];   // [bh][t][d]
__device__ __nv_bfloat16 g_kl[NBH * SEQ * HDIM];
__device__ __nv_bfloat16 g_vh[NBH * HDIM * SEQ];   // [bh][d][t]  (transposed)
__device__ __nv_bfloat16 g_vl[NBH * HDIM * SEQ];

// ---------------------------------------------------------------------------
// PTX helpers (arch-agnostic: valid on compute_103 / sm_103)
// ---------------------------------------------------------------------------
__device__ __forceinline__ uint32_t smem_u32(const void* p) {
    uint32_t a;
    asm("{ .reg .u64 t; cvta.to.shared.u64 t, %1; cvt.u32.u64 %0, t; }"
        : "=r"(a) : "l"(p));
    return a;
}

__device__ __forceinline__ void cp16(uint32_t saddr, const void* g) {
    asm volatile("cp.async.cg.shared.global [%0], [%1], 16;"
                 :: "r"(saddr), "l"(g) : "memory");
}

__device__ __forceinline__ void ldmx4(uint32_t* r, uint32_t addr) {
    asm volatile("ldmatrix.sync.aligned.m8n8.x4.shared.b16 {%0,%1,%2,%3}, [%4];"
                 : "=r"(r[0]), "=r"(r[1]), "=r"(r[2]), "=r"(r[3]) : "r"(addr));
}

__device__ __forceinline__ void mma_bf16(float* d, const uint32_t* a,
                                         const uint32_t* b) {
    asm volatile(
        "mma.sync.aligned.m16n8k16.row.col.f32.bf16.bf16.f32 "
        "{%0,%1,%2,%3}, {%4,%5,%6,%7}, {%8,%9}, {%0,%1,%2,%3};"
        : "+f"(d[0]), "+f"(d[1]), "+f"(d[2]), "+f"(d[3])
        : "r"(a[0]), "r"(a[1]), "r"(a[2]), "r"(a[3]), "r"(b[0]), "r"(b[1]));
}

__device__ __forceinline__ uint32_t packbf(float a, float b) {
    __nv_bfloat162 t = __floats2bfloat162_rn(a, b);
    return *(uint32_t*)&t;
}

// ---------------------------------------------------------------------------
// bf16 hi/lo split of x
// ---------------------------------------------------------------------------
__global__ void split_x(const float* __restrict__ in, int n) {
    int idx = (blockIdx.x * blockDim.x + threadIdx.x) * 4;
    if (idx >= n) return;
    float4 v = *(const float4*)(in + idx);
    __nv_bfloat16 h0 = __float2bfloat16(v.x);
    __nv_bfloat16 h1 = __float2bfloat16(v.y);
    __nv_bfloat16 h2 = __float2bfloat16(v.z);
    __nv_bfloat16 h3 = __float2bfloat16(v.w);
    __nv_bfloat16 l0 = __float2bfloat16(v.x - __bfloat162float(h0));
    __nv_bfloat16 l1 = __float2bfloat16(v.y - __bfloat162float(h1));
    __nv_bfloat16 l2 = __float2bfloat16(v.z - __bfloat162float(h2));
    __nv_bfloat16 l3 = __float2bfloat16(v.w - __bfloat162float(h3));
    __nv_bfloat162 a, b;
    a.x = h0; a.y = h1; b.x = h2; b.y = h3;
    *(__nv_bfloat162*)(g_xh + idx)     = a;
    *(__nv_bfloat162*)(g_xh + idx + 2) = b;
    a.x = l0; a.y = l1; b.x = l2; b.y = l3;
    *(__nv_bfloat162*)(g_xl + idx)     = a;
    *(__nv_bfloat162*)(g_xl + idx + 2) = b;
}

// Transpose + split: in [R, C] fp32 -> hi/lo [C, R] bf16
template <int WHICH>
__global__ void tsplit_kernel(const float* __restrict__ in, int R, int C) {
    __nv_bfloat16* hi = WHICH ? g_wph : g_wah;
    __nv_bfloat16* lo = WHICH ? g_wpl : g_wal;
    __shared__ float tile[32][33];
    int c0 = blockIdx.x * 32, r0 = blockIdx.y * 32;
    int tx = threadIdx.x, ty = threadIdx.y;
#pragma unroll
    for (int dy = 0; dy < 32; dy += 8)
        tile[ty + dy][tx] = in[(r0 + ty + dy) * C + c0 + tx];
    __syncthreads();
#pragma unroll
    for (int dy = 0; dy < 32; dy += 8) {
        int c = c0 + ty + dy, r = r0 + tx;
        float v = tile[tx][ty + dy];
        __nv_bfloat16 h = __float2bfloat16(v);
        __nv_bfloat16 l = __float2bfloat16(v - __bfloat162float(h));
        hi[(size_t)c * R + r] = h;
        lo[(size_t)c * R + r] = l;
    }
}

// ---------------------------------------------------------------------------
// HMMA GEMM: D[M,N] = A[M,768] @ B^T[N,768] (+bias), bf16 hi/lo split.
// CTA tile 128x128, BK=32, cp.async double-buffer, mma.sync m16n8k16.
// MODE 1: emit bf16 hi/lo q/k ([bh,t,d], q scaled) and transposed v ([bh,d,t])
// MODE 0: bias epilogue fp32 into Cout
// ---------------------------------------------------------------------------
#define BK        32
#define ROWB      80                       // padded row: 32*2 + 16 bytes
#define TILE_B    (128 * ROWB)             // 10240 B per operand tile
#define STAGE_B   (4 * TILE_B)             // Ah, Al, Bh, Bl = 40960 B
#define GEMM_SMEM (2 * STAGE_B)            // 81920 B
#define VP        136                      // v-transpose smem pitch (bf16)

template <int MODE>
__global__ __launch_bounds__(256)
void tc_gemm(const float* __restrict__ bias, float* __restrict__ Cout) {
    constexpr int N = MODE ? N_QKV : CDIM;
    constexpr int K = CDIM;
    constexpr int NCH = K / BK;            // 24

    const __nv_bfloat16* Ah = MODE ? g_xh : g_yh;
    const __nv_bfloat16* Al = MODE ? g_xl : g_yl;
    const __nv_bfloat16* Bh = MODE ? g_wah : g_wph;
    const __nv_bfloat16* Bl = MODE ? g_wal : g_wpl;

    extern __shared__ char smem[];
    const uint32_t sb = smem_u32(smem);

    const int tid  = threadIdx.x;
    const int lane = tid & 31;
    const int w    = tid >> 5;
    const int wm   = w & 3;
    const int wn   = w >> 2;
    const int m0   = blockIdx.y * 128;
    const int n0   = blockIdx.x * 128;

    float acc[2][8][4];
#pragma unroll
    for (int i = 0; i < 2; i++)
#pragma unroll
        for (int j = 0; j < 8; j++)
#pragma unroll
            for (int v = 0; v < 4; v++) acc[i][j][v] = 0.f;

    auto prefetch = [&](int c, int s) {
        const int k0 = c * BK;
        const uint32_t stage = sb + (uint32_t)s * STAGE_B;
#pragma unroll
        for (int t = 0; t < 8; t++) {
            int idx  = tid + t * 256;
            int tile = idx >> 9;
            int wi   = idx & 511;
            int r    = wi >> 2;
            int ch   = wi & 3;
            uint32_t saddr = stage + (uint32_t)tile * TILE_B + r * ROWB + ch * 16;
            const __nv_bfloat16* src;
            if (tile == 0)      src = Ah + (size_t)(m0 + r) * K + k0 + ch * 8;
            else if (tile == 1) src = Al + (size_t)(m0 + r) * K + k0 + ch * 8;
            else if (tile == 2) src = Bh + (size_t)(n0 + r) * K + k0 + ch * 8;
            else                src = Bl + (size_t)(n0 + r) * K + k0 + ch * 8;
            cp16(saddr, src);
        }
        asm volatile("cp.async.commit_group;" ::: "memory");
    };

    prefetch(0, 0);
    prefetch(1, 1);

    const uint32_t a_off =
        (uint32_t)(wm * 32 + (lane & 15)) * ROWB + ((lane >> 4) << 3) * 2;
    const uint32_t b_off =
        (uint32_t)(wn * 64 + (lane & 7) + ((lane >> 4) << 3)) * ROWB +
        (((lane >> 3) & 1) << 3) * 2;

    for (int c = 0; c < NCH; c++) {
        const int s = c & 1;
        if (c + 1 < NCH)
            asm volatile("cp.async.wait_group 1;" ::: "memory");
        else
            asm volatile("cp.async.wait_group 0;" ::: "memory");
        __syncthreads();

        const uint32_t stage = sb + (uint32_t)s * STAGE_B;
#pragma unroll
        for (int kk = 0; kk < BK; kk += 16) {
            uint32_t ah[2][4], al[2][4], bh[8][2], bl[8][2];
#pragma unroll
            for (int mi = 0; mi < 2; mi++) {
                uint32_t off = a_off + (uint32_t)(mi * 16) * ROWB + kk * 2;
                ldmx4(ah[mi], stage + off);
                ldmx4(al[mi], stage + TILE_B + off);
            }
#pragma unroll
            for (int np = 0; np < 4; np++) {
                uint32_t off = b_off + (uint32_t)(np * 16) * ROWB + kk * 2;
                uint32_t rh[4], rl[4];
                ldmx4(rh, stage + 2 * TILE_B + off);
                ldmx4(rl, stage + 3 * TILE_B + off);
                bh[2 * np][0] = rh[0]; bh[2 * np][1] = rh[1];
                bh[2 * np + 1][0] = rh[2]; bh[2 * np + 1][1] = rh[3];
                bl[2 * np][0] = rl[0]; bl[2 * np][1] = rl[1];
                bl[2 * np + 1][0] = rl[2]; bl[2 * np + 1][1] = rl[3];
            }
#pragma unroll
            for (int mi = 0; mi < 2; mi++)
#pragma unroll
                for (int ni = 0; ni < 8; ni++) {
                    mma_bf16(acc[mi][ni], ah[mi], bh[ni]);
                    mma_bf16(acc[mi][ni], ah[mi], bl[ni]);
                    mma_bf16(acc[mi][ni], al[mi], bh[ni]);
                }
        }
        __syncthreads();
        if (c + 2 < NCH) prefetch(c + 2, s);
    }

    // ---- epilogue ----
    const int mrow = m0 + wm * 32 + (lane >> 2);
    const int ncol = n0 + wn * 64 + 2 * (lane & 3);

    if (MODE == 0) {
#pragma unroll
        for (int mi = 0; mi < 2; mi++)
#pragma unroll
            for (int ni = 0; ni < 8; ni++) {
                const int n = ncol + ni * 8;
                const float b0 = bias[n], b1 = bias[n + 1];
#pragma unroll
                for (int half = 0; half < 2; half++) {
                    const int m = mrow + mi * 16 + half * 8;
                    float2 o;
                    o.x = acc[mi][ni][2 * half + 0] + b0;
                    o.y = acc[mi][ni][2 * half + 1] + b1;
                    *(float2*)(Cout + (size_t)m * N + n) = o;
                }
            }
        return;
    }

    // MODE 1: q/k direct bf16 hi/lo; v staged through smem (transpose)
    const int which = n0 / CDIM;            // 0=q 1=k 2=v, CTA-uniform
    const int bb = m0 >> 10;                // batch (CTA-uniform)
    const int t0 = m0 & 1023;

    if (which < 2) {
        __nv_bfloat16* dh = which == 0 ? g_qh : g_kh;
        __nv_bfloat16* dl = which == 0 ? g_ql : g_kl;
        const float scl = (which == 0) ? 0.125f : 1.0f;
#pragma unroll
        for (int mi = 0; mi < 2; mi++)
#pragma unroll
            for (int ni = 0; ni < 8; ni++) {
                const int n = ncol + ni * 8;
                const float b0 = bias[n], b1 = bias[n + 1];
                const int cloc = n - which * CDIM;
                const int h = cloc >> 6, d = cloc & 63;
#pragma unroll
                for (int half = 0; half < 2; half++) {
                    const int m = mrow + mi * 16 + half * 8;
                    const int t = m & 1023;
                    float a0 = (acc[mi][ni][2 * half + 0] + b0) * scl;
                    float a1 = (acc[mi][ni][2 * half + 1] + b1) * scl;
                    __nv_bfloat16 h0 = __float2bfloat16(a0);
                    __nv_bfloat16 h1 = __float2bfloat16(a1);
                    size_t idx = (((size_t)((m >> 10) * NHEAD + h) * SEQ + t)
                                  * HDIM + d);
                    *(uint32_t*)(dh + idx) = ((uint32_t)*(uint16_t*)&h1 << 16) |
                                             (uint32_t)*(uint16_t*)&h0;
                    *(uint32_t*)(dl + idx) =
                        packbf(a0 - __bfloat162float(h0),
                               a1 - __bfloat162float(h1));
                }
            }
    } else {
        // v: transpose via smem (CTA-local rows), coalesced [bh][d][t] writes
        __nv_bfloat16* svh = (__nv_bfloat16*)smem;
        __nv_bfloat16* svl = svh + 128 * VP;
        const int vch0 = n0 - 2 * CDIM;       // global v-channel base of tile
#pragma unroll
        for (int mi = 0; mi < 2; mi++)
#pragma unroll
            for (int ni = 0; ni < 8; ni++) {
                const int n = ncol + ni * 8;
                const float b0 = bias[n], b1 = bias[n + 1];
                const int cl = n - n0;            // CTA-local column 0..127
#pragma unroll
                for (int half = 0; half < 2; half++) {
                    const int ml = (mrow - m0) + mi * 16 + half * 8;
                    float a0 = acc[mi][ni][2 * half + 0] + b0;
                    float a1 = acc[mi][ni][2 * half + 1] + b1;
                    __nv_bfloat16 h0 = __float2bfloat16(a0);
                    __nv_bfloat16 h1 = __float2bfloat16(a1);
                    svh[cl * VP + ml]       = h0;
                    svh[(cl + 1) * VP + ml] = h1;
                    svl[cl * VP + ml]       =
                        __float2bfloat16(a0 - __bfloat162float(h0));
                    svl[(cl + 1) * VP + ml] =
                        __float2bfloat16(a1 - __bfloat162float(h1));
                }
            }
        __syncthreads();
        // Full 128x128 tile per array (16 iters -> 4096 uint4 chunks total;
        // the 8-iter version silently dropped t-rows 64..127 of V)
#pragma unroll
        for (int t = 0; t < 16; t++) {
            int idx = tid + t * 256;            // 0..4095
            int arr = idx >> 11;                // 0=hi 1=lo
            int wi  = idx & 2047;
            int r   = wi >> 4;                  // 0..127 (CTA-local channel)
            int ch  = wi & 15;                  // 0..15 (t chunk of 8)
            const __nv_bfloat16* s = (arr ? svl : svh) + r * VP + ch * 8;
            uint4 val = *(const uint4*)s;
            const int gc = vch0 + r;            // global v-channel 0..767
            const int h = gc >> 6, d = gc & 63;
            __nv_bfloat16* dst = (arr ? g_vl : g_vh) +
                (((size_t)(bb * NHEAD + h) * HDIM + d) * SEQ + t0 + ch * 8);
            *(uint4*)dst = val;
        }
    }
}

// ---------------------------------------------------------------------------
// Flash attention on HMMA. CTA: 64 q-rows x 4 warps (16 rows each), KV tile 64.
// cp.async double buffer, online softmax in C-fragments, P split hi/lo on the
// fly, V pre-transposed [bh][d][t]. Writes yh/yl bf16 directly.
// ---------------------------------------------------------------------------
#define ROWA      144                          // 64 bf16 = 128B + 16B pad
#define QTILE_B   (64 * ROWA)                  // 9216 B
#define ASTAGE_B  (4 * QTILE_B)                // kh,kl,vh,vl = 36864 B
#define ATTN_SMEM (2 * QTILE_B + 2 * ASTAGE_B) // 92160 B

__global__ __launch_bounds__(128)
void attn_kernel()
{
    extern __shared__ char smem[];
    const uint32_t sb = smem_u32(smem);

    const int bh = blockIdx.x;                 // 0..95
    const int qt = blockIdx.y;                 // 0..15
    const int q0 = qt * 64;
    const int tid  = threadIdx.x;
    const int lane = tid & 31;
    const int wm   = tid >> 5;                 // warp 0..3 -> q rows wm*16..+16
    const int nt   = qt + 1;                   // causal kv tiles

    // ---- stage Q (hi+lo) ----
#pragma unroll
    for (int t = 0; t < 8; t++) {
        int idx = tid + t * 128;               // 0..1023
        int tile = idx >> 9;                   // 0=hi 1=lo
        int wi = idx & 511;
        int r = wi >> 3, ch = wi & 7;
        const __nv_bfloat16* src = (tile ? g_ql : g_qh) +
            ((size_t)bh * SEQ + q0 + r) * HDIM + ch * 8;
        cp16(sb + tile * QTILE_B + r * ROWA + ch * 16, src);
    }
    asm volatile("cp.async.commit_group;" ::: "memory");

    auto prefetch = [&](int c, int s) {
        const int kv0 = c * 64;
        const uint32_t stage = sb + 2 * QTILE_B + (uint32_t)s * ASTAGE_B;
#pragma unroll
        for (int t = 0; t < 16; t++) {
            int idx = tid + t * 128;           // 0..2047
            int tile = idx >> 9;               // 0=kh 1=kl 2=vh 3=vl
            int wi = idx & 511;
            int r = wi >> 3, ch = wi & 7;
            const __nv_bfloat16* src;
            if (tile == 0)
                src = g_kh + ((size_t)bh * SEQ + kv0 + r) * HDIM + ch * 8;
            else if (tile == 1)
                src = g_kl + ((size_t)bh * SEQ + kv0 + r) * HDIM + ch * 8;
            else if (tile == 2)
                src = g_vh + ((size_t)bh * HDIM + r) * SEQ + kv0 + ch * 8;
            else
                src = g_vl + ((size_t)bh * HDIM + r) * SEQ + kv0 + ch * 8;
            cp16(stage + (uint32_t)tile * QTILE_B + r * ROWA + ch * 16, src);
        }
        asm volatile("cp.async.commit_group;" ::: "memory");
    };

    prefetch(0, 0);
    prefetch(nt > 1 ? 1 : 0, 1);

    // Q ready (<=2 pending -> Q group retired)
    asm volatile("cp.async.wait_group 2;" ::: "memory");
    __syncthreads();

    const uint32_t a_off =
        (uint32_t)(lane & 15) * ROWA + ((lane >> 4) << 3) * 2;
    const uint32_t b_off =
        (uint32_t)((lane & 7) + ((lane >> 4) << 3)) * ROWA +
        (((lane >> 3) & 1) << 3) * 2;

    uint32_t qhf[4][4], qlf[4][4];
#pragma unroll
    for (int ks = 0; ks < 4; ks++) {
        uint32_t off = (uint32_t)(wm * 16) * ROWA + a_off + ks * 32;
        ldmx4(qhf[ks], sb + off);
        ldmx4(qlf[ks], sb + QTILE_B + off);
    }

    float o[8][4];
#pragma unroll
    for (int i = 0; i < 8; i++)
#pragma unroll
        for (int j = 0; j < 4; j++) o[i][j] = 0.f;
    float m0 = -1e30f, m1 = -1e30f, l0 = 0.f, l1 = 0.f;

    const int r0 = lane >> 2;                  // local row within warp tile

    for (int kt = 0; kt < nt; kt++) {
        const int s = kt & 1;
        if (kt + 1 < nt)
            asm volatile("cp.async.wait_group 1;" ::: "memory");
        else
            asm volatile("cp.async.wait_group 0;" ::: "memory");
        __syncthreads();

        const uint32_t kb = sb + 2 * QTILE_B + (uint32_t)s * ASTAGE_B;
        const int kv0 = kt * 64;

        // ---- S = Q @ K^T (hi/lo 3-product) ----
        float s_[8][4];
#pragma unroll
        for (int i = 0; i < 8; i++)
#pragma unroll
            for (int j = 0; j < 4; j++) s_[i][j] = 0.f;

#pragma unroll
        for (int np = 0; np < 4; np++)
#pragma unroll
            for (int ks = 0; ks < 4; ks++) {
                uint32_t off = b_off + (uint32_t)(np * 16) * ROWA + ks * 32;
                uint32_t rh[4], rl[4];
                ldmx4(rh, kb + off);
                ldmx4(rl, kb + QTILE_B + off);
                mma_bf16(s_[2 * np],     qhf[ks], &rh[0]);
                mma_bf16(s_[2 * np],     qhf[ks], &rl[0]);
                mma_bf16(s_[2 * np],     qlf[ks], &rh[0]);
                mma_bf16(s_[2 * np + 1], qhf[ks], &rh[2]);
                mma_bf16(s_[2 * np + 1], qhf[ks], &rl[2]);
                mma_bf16(s_[2 * np + 1], qlf[ks], &rh[2]);
            }

        // ---- causal mask (diagonal tile only) ----
        if (kt == qt) {
            const int grow0 = q0 + wm * 16 + r0;
#pragma unroll
            for (int ni = 0; ni < 8; ni++) {
                const int col = kv0 + ni * 8 + 2 * (lane & 3);
                if (col > grow0)     s_[ni][0] = -1e30f;
                if (col + 1 > grow0) s_[ni][1] = -1e30f;
                if (col > grow0 + 8)     s_[ni][2] = -1e30f;
                if (col + 1 > grow0 + 8) s_[ni][3] = -1e30f;
            }
        }

        // ---- online softmax (rows r0, r0+8; quad = lanes sharing row) ----
        float mx0 = -1e30f, mx1 = -1e30f;
#pragma unroll
        for (int ni = 0; ni < 8; ni++) {
            mx0 = fmaxf(mx0, fmaxf(s_[ni][0], s_[ni][1]));
            mx1 = fmaxf(mx1, fmaxf(s_[ni][2], s_[ni][3]));
        }
        mx0 = fmaxf(mx0, __shfl_xor_sync(0xffffffffu, mx0, 1));
        mx0 = fmaxf(mx0, __shfl_xor_sync(0xffffffffu, mx0, 2));
        mx1 = fmaxf(mx1, __shfl_xor_sync(0xffffffffu, mx1, 1));
        mx1 = fmaxf(mx1, __shfl_xor_sync(0xffffffffu, mx1, 2));
        const float mn0 = fmaxf(m0, mx0), mn1 = fmaxf(m1, mx1);
        const float al0 = __expf(m0 - mn0), al1 = __expf(m1 - mn1);
        float rs0 = 0.f, rs1 = 0.f;
#pragma unroll
        for (int ni = 0; ni < 8; ni++) {
            s_[ni][0] = __expf(s_[ni][0] - mn0);
            s_[ni][1] = __expf(s_[ni][1] - mn0);
            s_[ni][2] = __expf(s_[ni][2] - mn1);
            s_[ni][3] = __expf(s_[ni][3] - mn1);
            rs0 += s_[ni][0] + s_[ni][1];
            rs1 += s_[ni][2] + s_[ni][3];
        }
        rs0 += __shfl_xor_sync(0xffffffffu, rs0, 1);
        rs0 += __shfl_xor_sync(0xffffffffu, rs0, 2);
        rs1 += __shfl_xor_sync(0xffffffffu, rs1, 1);
        rs1 += __shfl_xor_sync(0xffffffffu, rs1, 2);
        l0 = l0 * al0 + rs0; l1 = l1 * al1 + rs1;
        m0 = mn0; m1 = mn1;
#pragma unroll
        for (int ni = 0; ni < 8; ni++) {
            o[ni][0] *= al0; o[ni][1] *= al0;
            o[ni][2] *= al1; o[ni][3] *= al1;
        }

        // ---- P fragments (hi/lo) ----
        uint32_t phf[4][4], plf[4][4];
#pragma unroll
        for (int j = 0; j < 4; j++)
#pragma unroll
            for (int half = 0; half < 2; half++) {
                const float* sv = s_[2 * j + half];
                __nv_bfloat16 h0 = __float2bfloat16(sv[0]);
                __nv_bfloat16 h1 = __float2bfloat16(sv[1]);
                __nv_bfloat16 h2 = __float2bfloat16(sv[2]);
                __nv_bfloat16 h3 = __float2bfloat16(sv[3]);
                phf[j][2 * half]     = ((uint32_t)*(uint16_t*)&h1 << 16) |
                                       (uint32_t)*(uint16_t*)&h0;
                phf[j][2 * half + 1] = ((uint32_t)*(uint16_t*)&h3 << 16) |
                                       (uint32_t)*(uint16_t*)&h2;
                plf[j][2 * half] = packbf(sv[0] - __bfloat162float(h0),
                                          sv[1] - __bfloat162float(h1));
                plf[j][2 * half + 1] = packbf(sv[2] - __bfloat162float(h2),
                                              sv[3] - __bfloat162float(h3));
            }

        // ---- O += P @ V (hi/lo 3-product); V^T tile rows=d, cols=kv ----
#pragma unroll
        for (int np = 0; np < 4; np++)
#pragma unroll
            for (int ks = 0; ks < 4; ks++) {
                uint32_t off = b_off + (uint32_t)(np * 16) * ROWA + ks * 32;
                uint32_t rh[4], rl[4];
                ldmx4(rh, kb + 2 * QTILE_B + off);
                ldmx4(rl, kb + 3 * QTILE_B + off);
                mma_bf16(o[2 * np],     phf[ks], &rh[0]);
                mma_bf16(o[2 * np],     phf[ks], &rl[0]);
                mma_bf16(o[2 * np],     plf[ks], &rh[0]);
                mma_bf16(o[2 * np + 1], phf[ks], &rh[2]);
                mma_bf16(o[2 * np + 1], phf[ks], &rl[2]);
                mma_bf16(o[2 * np + 1], plf[ks], &rh[2]);
            }

        __syncthreads();
        if (kt + 2 < nt) prefetch(kt + 2, s);
    }

    // ---- epilogue: y = o / l, write bf16 hi/lo ----
    const int b = bh / NHEAD, h = bh % NHEAD;
    const float inv0 = 1.f / l0, inv1 = 1.f / l1;
    const int t_0 = q0 + wm * 16 + r0;
#pragma unroll
    for (int ni = 0; ni < 8; ni++) {
        const int d = ni * 8 + 2 * (lane & 3);
#pragma unroll
        for (int half = 0; half < 2; half++) {
            const int t = t_0 + half * 8;
            const float inv = half ? inv1 : inv0;
            float a0 = o[ni][2 * half + 0] * inv;
            float a1 = o[ni][2 * half + 1] * inv;
            __nv_bfloat16 h0 = __float2bfloat16(a0);
            __nv_bfloat16 h1 = __float2bfloat16(a1);
            size_t idx = ((size_t)b * SEQ + t) * CDIM + h * HDIM + d;
            *(uint32_t*)(g_yh + idx) = ((uint32_t)*(uint16_t*)&h1 << 16) |
                                       (uint32_t)*(uint16_t*)&h0;
            *(uint32_t*)(g_yl + idx) = packbf(a0 - __bfloat162float(h0),
                                              a1 - __bfloat162float(h1));
        }
    }
}

// ---------------------------------------------------------------------------
extern "C" void kernel_launch(void* const* d_in, const int* in_sizes, int n_in,
                              void* d_out, int out_size)
{
    const float* x  = (const float*)d_in[0];
    const float* Wa = (const float*)d_in[1];
    const float* ba = (const float*)d_in[2];
    const float* Wp = (const float*)d_in[3];
    const float* bp = (const float*)d_in[4];
    float* out = (float*)d_out;

    cudaFuncSetAttribute(attn_kernel,
                         cudaFuncAttributeMaxDynamicSharedMemorySize, ATTN_SMEM);
    cudaFuncSetAttribute(tc_gemm<1>,
                         cudaFuncAttributeMaxDynamicSharedMemorySize, GEMM_SMEM);
    cudaFuncSetAttribute(tc_gemm<0>,
                         cudaFuncAttributeMaxDynamicSharedMemorySize, GEMM_SMEM);

    const int nx = MTOT * CDIM;

    // 1) bf16 hi/lo splits of x and the (transposed) weights
    split_x<<<nx / 1024, 256>>>(x, nx);
    tsplit_kernel<0><<<dim3(N_QKV / 32, CDIM / 32), dim3(32, 8)>>>(Wa, CDIM, N_QKV);
    tsplit_kernel<1><<<dim3(CDIM / 32, CDIM / 32), dim3(32, 8)>>>(Wp, CDIM, CDIM);

    // 2) QKV projection -> bf16 hi/lo q/k ([bh,t,d]) + transposed v ([bh,d,t])
    tc_gemm<1><<<dim3(N_QKV / 128, MTOT / 128), 256, GEMM_SMEM>>>(ba, nullptr);

    // 3) Causal flash attention on HMMA -> yh/yl bf16
    attn_kernel<<<dim3(NBH, SEQ / 64), 128, ATTN_SMEM>>>();

    // 4) Output projection
    tc_gemm<0><<<dim3(CDIM / 128, MTOT / 128), 256, GEMM_SMEM>>>(bp, out);
}

// round 12
// speedup vs baseline: 2.9987x; 1.0851x over previous
#include <cuda_runtime.h>
#include <cuda_bf16.h>
#include <cstdint>
#include <math.h>

// Problem constants
#define BATCH 8
#define SEQ   1024
#define CDIM  768
#define NHEAD 12
#define HDIM  64
#define MTOT  (BATCH * SEQ)      // 8192
#define N_QKV (3 * CDIM)         // 2304
#define NBH   (BATCH * NHEAD)    // 96

// ---------------------------------------------------------------------------
// Scratch (allocation-free rule: __device__ globals)
// ---------------------------------------------------------------------------
// bf16 hi/lo split operands
__device__ __nv_bfloat16 g_xh[MTOT * CDIM];
__device__ __nv_bfloat16 g_xl[MTOT * CDIM];
__device__ __nv_bfloat16 g_yh[MTOT * CDIM];
__device__ __nv_bfloat16 g_yl[MTOT * CDIM];
__device__ __nv_bfloat16 g_wah[N_QKV * CDIM];   // W_attn^T  [N=2304, K=768]
__device__ __nv_bfloat16 g_wal[N_QKV * CDIM];
__device__ __nv_bfloat16 g_wph[CDIM * CDIM];    // W_proj^T  [N=768,  K=768]
__device__ __nv_bfloat16 g_wpl[CDIM * CDIM];
// attention operands, bf16 hi/lo, per-head layouts
__device__ __nv_bfloat16 g_qh[NBH * SEQ * HDIM];   // [bh][t][d] (q pre-scaled)
__device__ __nv_bfloat16 g_ql[NBH * SEQ * HDIM];
__device__ __nv_bfloat16 g_kh[NBH * SEQ * HDIM];   // [bh][t][d]
__device__ __nv_bfloat16 g_kl[NBH * SEQ * HDIM];
__device__ __nv_bfloat16 g_vh[NBH * HDIM * SEQ];   // [bh][d][t]  (transposed)
__device__ __nv_bfloat16 g_vl[NBH * HDIM * SEQ];

// ---------------------------------------------------------------------------
// PTX helpers (arch-agnostic: valid on compute_103 / sm_103)
// ---------------------------------------------------------------------------
__device__ __forceinline__ uint32_t smem_u32(const void* p) {
    uint32_t a;
    asm("{ .reg .u64 t; cvta.to.shared.u64 t, %1; cvt.u32.u64 %0, t; }"
        : "=r"(a) : "l"(p));
    return a;
}

__device__ __forceinline__ void cp16(uint32_t saddr, const void* g) {
    asm volatile("cp.async.cg.shared.global [%0], [%1], 16;"
                 :: "r"(saddr), "l"(g) : "memory");
}

__device__ __forceinline__ void ldmx4(uint32_t* r, uint32_t addr) {
    asm volatile("ldmatrix.sync.aligned.m8n8.x4.shared.b16 {%0,%1,%2,%3}, [%4];"
                 : "=r"(r[0]), "=r"(r[1]), "=r"(r[2]), "=r"(r[3]) : "r"(addr));
}

__device__ __forceinline__ void mma_bf16(float* d, const uint32_t* a,
                                         const uint32_t* b) {
    asm volatile(
        "mma.sync.aligned.m16n8k16.row.col.f32.bf16.bf16.f32 "
        "{%0,%1,%2,%3}, {%4,%5,%6,%7}, {%8,%9}, {%0,%1,%2,%3};"
        : "+f"(d[0]), "+f"(d[1]), "+f"(d[2]), "+f"(d[3])
        : "r"(a[0]), "r"(a[1]), "r"(a[2]), "r"(a[3]), "r"(b[0]), "r"(b[1]));
}

__device__ __forceinline__ uint32_t packbf(float a, float b) {
    __nv_bfloat162 t = __floats2bfloat162_rn(a, b);
    return *(uint32_t*)&t;
}

// ---------------------------------------------------------------------------
// bf16 hi/lo split of x
// ---------------------------------------------------------------------------
__global__ void split_x(const float* __restrict__ in, int n) {
    int idx = (blockIdx.x * blockDim.x + threadIdx.x) * 4;
    if (idx >= n) return;
    float4 v = *(const float4*)(in + idx);
    __nv_bfloat16 h0 = __float2bfloat16(v.x);
    __nv_bfloat16 h1 = __float2bfloat16(v.y);
    __nv_bfloat16 h2 = __float2bfloat16(v.z);
    __nv_bfloat16 h3 = __float2bfloat16(v.w);
    __nv_bfloat16 l0 = __float2bfloat16(v.x - __bfloat162float(h0));
    __nv_bfloat16 l1 = __float2bfloat16(v.y - __bfloat162float(h1));
    __nv_bfloat16 l2 = __float2bfloat16(v.z - __bfloat162float(h2));
    __nv_bfloat16 l3 = __float2bfloat16(v.w - __bfloat162float(h3));
    __nv_bfloat162 a, b;
    a.x = h0; a.y = h1; b.x = h2; b.y = h3;
    *(__nv_bfloat162*)(g_xh + idx)     = a;
    *(__nv_bfloat162*)(g_xh + idx + 2) = b;
    a.x = l0; a.y = l1; b.x = l2; b.y = l3;
    *(__nv_bfloat162*)(g_xl + idx)     = a;
    *(__nv_bfloat162*)(g_xl + idx + 2) = b;
}

// Transpose + split: in [R, C] fp32 -> hi/lo [C, R] bf16
template <int WHICH>
__global__ void tsplit_kernel(const float* __restrict__ in, int R, int C) {
    __nv_bfloat16* hi = WHICH ? g_wph : g_wah;
    __nv_bfloat16* lo = WHICH ? g_wpl : g_wal;
    __shared__ float tile[32][33];
    int c0 = blockIdx.x * 32, r0 = blockIdx.y * 32;
    int tx = threadIdx.x, ty = threadIdx.y;
#pragma unroll
    for (int dy = 0; dy < 32; dy += 8)
        tile[ty + dy][tx] = in[(r0 + ty + dy) * C + c0 + tx];
    __syncthreads();
#pragma unroll
    for (int dy = 0; dy < 32; dy += 8) {
        int c = c0 + ty + dy, r = r0 + tx;
        float v = tile[tx][ty + dy];
        __nv_bfloat16 h = __float2bfloat16(v);
        __nv_bfloat16 l = __float2bfloat16(v - __bfloat162float(h));
        hi[(size_t)c * R + r] = h;
        lo[(size_t)c * R + r] = l;
    }
}

// ---------------------------------------------------------------------------
// HMMA GEMM: D[M,N] = A[M,768] @ B^T[N,768] (+bias), bf16 hi/lo split.
// CTA tile 128x128, BK=32, cp.async double-buffer, mma.sync m16n8k16.
// __launch_bounds__(256, 2): cap regs at 128 so 2 CTAs/SM fit the regfile
// (R11 measured 140 regs -> 1 CTA/SM -> occ 12.4%, tc_gemm<1> 238->298us).
// MODE 1: emit bf16 hi/lo q/k ([bh,t,d], q scaled) and transposed v ([bh,d,t])
// MODE 0: bias epilogue fp32 into Cout
// ---------------------------------------------------------------------------
#define BK        32
#define ROWB      80                       // padded row: 32*2 + 16 bytes
#define TILE_B    (128 * ROWB)             // 10240 B per operand tile
#define STAGE_B   (4 * TILE_B)             // Ah, Al, Bh, Bl = 40960 B
#define GEMM_SMEM (2 * STAGE_B)            // 81920 B
#define VP        136                      // v-transpose smem pitch (bf16)

template <int MODE>
__global__ __launch_bounds__(256, 2)
void tc_gemm(const float* __restrict__ bias, float* __restrict__ Cout) {
    constexpr int N = MODE ? N_QKV : CDIM;
    constexpr int K = CDIM;
    constexpr int NCH = K / BK;            // 24

    const __nv_bfloat16* Ah = MODE ? g_xh : g_yh;
    const __nv_bfloat16* Al = MODE ? g_xl : g_yl;
    const __nv_bfloat16* Bh = MODE ? g_wah : g_wph;
    const __nv_bfloat16* Bl = MODE ? g_wal : g_wpl;

    extern __shared__ char smem[];
    const uint32_t sb = smem_u32(smem);

    const int tid  = threadIdx.x;
    const int lane = tid & 31;
    const int w    = tid >> 5;
    const int wm   = w & 3;
    const int wn   = w >> 2;
    const int m0   = blockIdx.y * 128;
    const int n0   = blockIdx.x * 128;

    float acc[2][8][4];
#pragma unroll
    for (int i = 0; i < 2; i++)
#pragma unroll
        for (int j = 0; j < 8; j++)
#pragma unroll
            for (int v = 0; v < 4; v++) acc[i][j][v] = 0.f;

    auto prefetch = [&](int c, int s) {
        const int k0 = c * BK;
        const uint32_t stage = sb + (uint32_t)s * STAGE_B;
#pragma unroll
        for (int t = 0; t < 8; t++) {
            int idx  = tid + t * 256;
            int tile = idx >> 9;
            int wi   = idx & 511;
            int r    = wi >> 2;
            int ch   = wi & 3;
            uint32_t saddr = stage + (uint32_t)tile * TILE_B + r * ROWB + ch * 16;
            const __nv_bfloat16* src;
            if (tile == 0)      src = Ah + (size_t)(m0 + r) * K + k0 + ch * 8;
            else if (tile == 1) src = Al + (size_t)(m0 + r) * K + k0 + ch * 8;
            else if (tile == 2) src = Bh + (size_t)(n0 + r) * K + k0 + ch * 8;
            else                src = Bl + (size_t)(n0 + r) * K + k0 + ch * 8;
            cp16(saddr, src);
        }
        asm volatile("cp.async.commit_group;" ::: "memory");
    };

    prefetch(0, 0);
    prefetch(1, 1);

    const uint32_t a_off =
        (uint32_t)(wm * 32 + (lane & 15)) * ROWB + ((lane >> 4) << 3) * 2;
    const uint32_t b_off =
        (uint32_t)(wn * 64 + (lane & 7) + ((lane >> 4) << 3)) * ROWB +
        (((lane >> 3) & 1) << 3) * 2;

    for (int c = 0; c < NCH; c++) {
        const int s = c & 1;
        if (c + 1 < NCH)
            asm volatile("cp.async.wait_group 1;" ::: "memory");
        else
            asm volatile("cp.async.wait_group 0;" ::: "memory");
        __syncthreads();

        const uint32_t stage = sb + (uint32_t)s * STAGE_B;
#pragma unroll
        for (int kk = 0; kk < BK; kk += 16) {
            uint32_t ah[2][4], al[2][4], bh[8][2], bl[8][2];
#pragma unroll
            for (int mi = 0; mi < 2; mi++) {
                uint32_t off = a_off + (uint32_t)(mi * 16) * ROWB + kk * 2;
                ldmx4(ah[mi], stage + off);
                ldmx4(al[mi], stage + TILE_B + off);
            }
#pragma unroll
            for (int np = 0; np < 4; np++) {
                uint32_t off = b_off + (uint32_t)(np * 16) * ROWB + kk * 2;
                uint32_t rh[4], rl[4];
                ldmx4(rh, stage + 2 * TILE_B + off);
                ldmx4(rl, stage + 3 * TILE_B + off);
                bh[2 * np][0] = rh[0]; bh[2 * np][1] = rh[1];
                bh[2 * np + 1][0] = rh[2]; bh[2 * np + 1][1] = rh[3];
                bl[2 * np][0] = rl[0]; bl[2 * np][1] = rl[1];
                bl[2 * np + 1][0] = rl[2]; bl[2 * np + 1][1] = rl[3];
            }
#pragma unroll
            for (int mi = 0; mi < 2; mi++)
#pragma unroll
                for (int ni = 0; ni < 8; ni++) {
                    mma_bf16(acc[mi][ni], ah[mi], bh[ni]);
                    mma_bf16(acc[mi][ni], ah[mi], bl[ni]);
                    mma_bf16(acc[mi][ni], al[mi], bh[ni]);
                }
        }
        __syncthreads();
        if (c + 2 < NCH) prefetch(c + 2, s);
    }

    // ---- epilogue ----
    const int mrow = m0 + wm * 32 + (lane >> 2);
    const int ncol = n0 + wn * 64 + 2 * (lane & 3);

    if (MODE == 0) {
#pragma unroll
        for (int mi = 0; mi < 2; mi++)
#pragma unroll
            for (int ni = 0; ni < 8; ni++) {
                const int n = ncol + ni * 8;
                const float b0 = bias[n], b1 = bias[n + 1];
#pragma unroll
                for (int half = 0; half < 2; half++) {
                    const int m = mrow + mi * 16 + half * 8;
                    float2 o;
                    o.x = acc[mi][ni][2 * half + 0] + b0;
                    o.y = acc[mi][ni][2 * half + 1] + b1;
                    *(float2*)(Cout + (size_t)m * N + n) = o;
                }
            }
        return;
    }

    // MODE 1: q/k direct bf16 hi/lo; v staged through smem (transpose)
    const int which = n0 / CDIM;            // 0=q 1=k 2=v, CTA-uniform
    const int bb = m0 >> 10;                // batch (CTA-uniform)
    const int t0 = m0 & 1023;

    if (which < 2) {
        __nv_bfloat16* dh = which == 0 ? g_qh : g_kh;
        __nv_bfloat16* dl = which == 0 ? g_ql : g_kl;
        const float scl = (which == 0) ? 0.125f : 1.0f;
#pragma unroll
        for (int mi = 0; mi < 2; mi++)
#pragma unroll
            for (int ni = 0; ni < 8; ni++) {
                const int n = ncol + ni * 8;
                const float b0 = bias[n], b1 = bias[n + 1];
                const int cloc = n - which * CDIM;
                const int h = cloc >> 6, d = cloc & 63;
#pragma unroll
                for (int half = 0; half < 2; half++) {
                    const int m = mrow + mi * 16 + half * 8;
                    const int t = m & 1023;
                    float a0 = (acc[mi][ni][2 * half + 0] + b0) * scl;
                    float a1 = (acc[mi][ni][2 * half + 1] + b1) * scl;
                    __nv_bfloat16 h0 = __float2bfloat16(a0);
                    __nv_bfloat16 h1 = __float2bfloat16(a1);
                    size_t idx = (((size_t)((m >> 10) * NHEAD + h) * SEQ + t)
                                  * HDIM + d);
                    *(uint32_t*)(dh + idx) = ((uint32_t)*(uint16_t*)&h1 << 16) |
                                             (uint32_t)*(uint16_t*)&h0;
                    *(uint32_t*)(dl + idx) =
                        packbf(a0 - __bfloat162float(h0),
                               a1 - __bfloat162float(h1));
                }
            }
    } else {
        // v: transpose via smem (CTA-local rows), coalesced [bh][d][t] writes
        __nv_bfloat16* svh = (__nv_bfloat16*)smem;
        __nv_bfloat16* svl = svh + 128 * VP;
        const int vch0 = n0 - 2 * CDIM;       // global v-channel base of tile
#pragma unroll
        for (int mi = 0; mi < 2; mi++)
#pragma unroll
            for (int ni = 0; ni < 8; ni++) {
                const int n = ncol + ni * 8;
                const float b0 = bias[n], b1 = bias[n + 1];
                const int cl = n - n0;            // CTA-local column 0..127
#pragma unroll
                for (int half = 0; half < 2; half++) {
                    const int ml = (mrow - m0) + mi * 16 + half * 8;
                    float a0 = acc[mi][ni][2 * half + 0] + b0;
                    float a1 = acc[mi][ni][2 * half + 1] + b1;
                    __nv_bfloat16 h0 = __float2bfloat16(a0);
                    __nv_bfloat16 h1 = __float2bfloat16(a1);
                    svh[cl * VP + ml]       = h0;
                    svh[(cl + 1) * VP + ml] = h1;
                    svl[cl * VP + ml]       =
                        __float2bfloat16(a0 - __bfloat162float(h0));
                    svl[(cl + 1) * VP + ml] =
                        __float2bfloat16(a1 - __bfloat162float(h1));
                }
            }
        __syncthreads();
        // Full 128x128 tile per array (16 iters -> 4096 uint4 chunks total)
#pragma unroll
        for (int t = 0; t < 16; t++) {
            int idx = tid + t * 256;            // 0..4095
            int arr = idx >> 11;                // 0=hi 1=lo
            int wi  = idx & 2047;
            int r   = wi >> 4;                  // 0..127 (CTA-local channel)
            int ch  = wi & 15;                  // 0..15 (t chunk of 8)
            const __nv_bfloat16* s = (arr ? svl : svh) + r * VP + ch * 8;
            uint4 val = *(const uint4*)s;
            const int gc = vch0 + r;            // global v-channel 0..767
            const int h = gc >> 6, d = gc & 63;
            __nv_bfloat16* dst = (arr ? g_vl : g_vh) +
                (((size_t)(bb * NHEAD + h) * HDIM + d) * SEQ + t0 + ch * 8);
            *(uint4*)dst = val;
        }
    }
}

// ---------------------------------------------------------------------------
// Flash attention on HMMA. CTA: 64 q-rows x 4 warps (16 rows each), KV tile 64.
// cp.async double buffer, online softmax in C-fragments, P split hi/lo on the
// fly, V pre-transposed [bh][d][t]. Writes yh/yl bf16 directly.
// ---------------------------------------------------------------------------
#define ROWA      144                          // 64 bf16 = 128B + 16B pad
#define QTILE_B   (64 * ROWA)                  // 9216 B
#define ASTAGE_B  (4 * QTILE_B)                // kh,kl,vh,vl = 36864 B
#define ATTN_SMEM (2 * QTILE_B + 2 * ASTAGE_B) // 92160 B

__global__ __launch_bounds__(128)
void attn_kernel()
{
    extern __shared__ char smem[];
    const uint32_t sb = smem_u32(smem);

    const int bh = blockIdx.x;                 // 0..95
    const int qt = blockIdx.y;                 // 0..15
    const int q0 = qt * 64;
    const int tid  = threadIdx.x;
    const int lane = tid & 31;
    const int wm   = tid >> 5;                 // warp 0..3 -> q rows wm*16..+16
    const int nt   = qt + 1;                   // causal kv tiles

    // ---- stage Q (hi+lo) ----
#pragma unroll
    for (int t = 0; t < 8; t++) {
        int idx = tid + t * 128;               // 0..1023
        int tile = idx >> 9;                   // 0=hi 1=lo
        int wi = idx & 511;
        int r = wi >> 3, ch = wi & 7;
        const __nv_bfloat16* src = (tile ? g_ql : g_qh) +
            ((size_t)bh * SEQ + q0 + r) * HDIM + ch * 8;
        cp16(sb + tile * QTILE_B + r * ROWA + ch * 16, src);
    }
    asm volatile("cp.async.commit_group;" ::: "memory");

    auto prefetch = [&](int c, int s) {
        const int kv0 = c * 64;
        const uint32_t stage = sb + 2 * QTILE_B + (uint32_t)s * ASTAGE_B;
#pragma unroll
        for (int t = 0; t < 16; t++) {
            int idx = tid + t * 128;           // 0..2047
            int tile = idx >> 9;               // 0=kh 1=kl 2=vh 3=vl
            int wi = idx & 511;
            int r = wi >> 3, ch = wi & 7;
            const __nv_bfloat16* src;
            if (tile == 0)
                src = g_kh + ((size_t)bh * SEQ + kv0 + r) * HDIM + ch * 8;
            else if (tile == 1)
                src = g_kl + ((size_t)bh * SEQ + kv0 + r) * HDIM + ch * 8;
            else if (tile == 2)
                src = g_vh + ((size_t)bh * HDIM + r) * SEQ + kv0 + ch * 8;
            else
                src = g_vl + ((size_t)bh * HDIM + r) * SEQ + kv0 + ch * 8;
            cp16(stage + (uint32_t)tile * QTILE_B + r * ROWA + ch * 16, src);
        }
        asm volatile("cp.async.commit_group;" ::: "memory");
    };

    prefetch(0, 0);
    prefetch(nt > 1 ? 1 : 0, 1);

    // Q ready (<=2 pending -> Q group retired)
    asm volatile("cp.async.wait_group 2;" ::: "memory");
    __syncthreads();

    const uint32_t a_off =
        (uint32_t)(lane & 15) * ROWA + ((lane >> 4) << 3) * 2;
    const uint32_t b_off =
        (uint32_t)((lane & 7) + ((lane >> 4) << 3)) * ROWA +
        (((lane >> 3) & 1) << 3) * 2;

    uint32_t qhf[4][4], qlf[4][4];
#pragma unroll
    for (int ks = 0; ks < 4; ks++) {
        uint32_t off = (uint32_t)(wm * 16) * ROWA + a_off + ks * 32;
        ldmx4(qhf[ks], sb + off);
        ldmx4(qlf[ks], sb + QTILE_B + off);
    }

    float o[8][4];
#pragma unroll
    for (int i = 0; i < 8; i++)
#pragma unroll
        for (int j = 0; j < 4; j++) o[i][j] = 0.f;
    float m0 = -1e30f, m1 = -1e30f, l0 = 0.f, l1 = 0.f;

    const int r0 = lane >> 2;                  // local row within warp tile

    for (int kt = 0; kt < nt; kt++) {
        const int s = kt & 1;
        if (kt + 1 < nt)
            asm volatile("cp.async.wait_group 1;" ::: "memory");
        else
            asm volatile("cp.async.wait_group 0;" ::: "memory");
        __syncthreads();

        const uint32_t kb = sb + 2 * QTILE_B + (uint32_t)s * ASTAGE_B;
        const int kv0 = kt * 64;

        // ---- S = Q @ K^T (hi/lo 3-product) ----
        float s_[8][4];
#pragma unroll
        for (int i = 0; i < 8; i++)
#pragma unroll
            for (int j = 0; j < 4; j++) s_[i][j] = 0.f;

#pragma unroll
        for (int np = 0; np < 4; np++)
#pragma unroll
            for (int ks = 0; ks < 4; ks++) {
                uint32_t off = b_off + (uint32_t)(np * 16) * ROWA + ks * 32;
                uint32_t rh[4], rl[4];
                ldmx4(rh, kb + off);
                ldmx4(rl, kb + QTILE_B + off);
                mma_bf16(s_[2 * np],     qhf[ks], &rh[0]);
                mma_bf16(s_[2 * np],     qhf[ks], &rl[0]);
                mma_bf16(s_[2 * np],     qlf[ks], &rh[0]);
                mma_bf16(s_[2 * np + 1], qhf[ks], &rh[2]);
                mma_bf16(s_[2 * np + 1], qhf[ks], &rl[2]);
                mma_bf16(s_[2 * np + 1], qlf[ks], &rh[2]);
            }

        // ---- causal mask (diagonal tile only) ----
        if (kt == qt) {
            const int grow0 = q0 + wm * 16 + r0;
#pragma unroll
            for (int ni = 0; ni < 8; ni++) {
                const int col = kv0 + ni * 8 + 2 * (lane & 3);
                if (col > grow0)     s_[ni][0] = -1e30f;
                if (col + 1 > grow0) s_[ni][1] = -1e30f;
                if (col > grow0 + 8)     s_[ni][2] = -1e30f;
                if (col + 1 > grow0 + 8) s_[ni][3] = -1e30f;
            }
        }

        // ---- online softmax (rows r0, r0+8; quad = lanes sharing row) ----
        float mx0 = -1e30f, mx1 = -1e30f;
#pragma unroll
        for (int ni = 0; ni < 8; ni++) {
            mx0 = fmaxf(mx0, fmaxf(s_[ni][0], s_[ni][1]));
            mx1 = fmaxf(mx1, fmaxf(s_[ni][2], s_[ni][3]));
        }
        mx0 = fmaxf(mx0, __shfl_xor_sync(0xffffffffu, mx0, 1));
        mx0 = fmaxf(mx0, __shfl_xor_sync(0xffffffffu, mx0, 2));
        mx1 = fmaxf(mx1, __shfl_xor_sync(0xffffffffu, mx1, 1));
        mx1 = fmaxf(mx1, __shfl_xor_sync(0xffffffffu, mx1, 2));
        const float mn0 = fmaxf(m0, mx0), mn1 = fmaxf(m1, mx1);
        const float al0 = __expf(m0 - mn0), al1 = __expf(m1 - mn1);
        float rs0 = 0.f, rs1 = 0.f;
#pragma unroll
        for (int ni = 0; ni < 8; ni++) {
            s_[ni][0] = __expf(s_[ni][0] - mn0);
            s_[ni][1] = __expf(s_[ni][1] - mn0);
            s_[ni][2] = __expf(s_[ni][2] - mn1);
            s_[ni][3] = __expf(s_[ni][3] - mn1);
            rs0 += s_[ni][0] + s_[ni][1];
            rs1 += s_[ni][2] + s_[ni][3];
        }
        rs0 += __shfl_xor_sync(0xffffffffu, rs0, 1);
        rs0 += __shfl_xor_sync(0xffffffffu, rs0, 2);
        rs1 += __shfl_xor_sync(0xffffffffu, rs1, 1);
        rs1 += __shfl_xor_sync(0xffffffffu, rs1, 2);
        l0 = l0 * al0 + rs0; l1 = l1 * al1 + rs1;
        m0 = mn0; m1 = mn1;
#pragma unroll
        for (int ni = 0; ni < 8; ni++) {
            o[ni][0] *= al0; o[ni][1] *= al0;
            o[ni][2] *= al1; o[ni][3] *= al1;
        }

        // ---- P fragments (hi/lo) ----
        uint32_t phf[4][4], plf[4][4];
#pragma unroll
        for (int j = 0; j < 4; j++)
#pragma unroll
            for (int half = 0; half < 2; half++) {
                const float* sv = s_[2 * j + half];
                __nv_bfloat16 h0 = __float2bfloat16(sv[0]);
                __nv_bfloat16 h1 = __float2bfloat16(sv[1]);
                __nv_bfloat16 h2 = __float2bfloat16(sv[2]);
                __nv_bfloat16 h3 = __float2bfloat16(sv[3]);
                phf[j][2 * half]     = ((uint32_t)*(uint16_t*)&h1 << 16) |
                                       (uint32_t)*(uint16_t*)&h0;
                phf[j][2 * half + 1] = ((uint32_t)*(uint16_t*)&h3 << 16) |
                                       (uint32_t)*(uint16_t*)&h2;
                plf[j][2 * half] = packbf(sv[0] - __bfloat162float(h0),
                                          sv[1] - __bfloat162float(h1));
                plf[j][2 * half + 1] = packbf(sv[2] - __bfloat162float(h2),
                                              sv[3] - __bfloat162float(h3));
            }

        // ---- O += P @ V (hi/lo 3-product); V^T tile rows=d, cols=kv ----
#pragma unroll
        for (int np = 0; np < 4; np++)
#pragma unroll
            for (int ks = 0; ks < 4; ks++) {
                uint32_t off = b_off + (uint32_t)(np * 16) * ROWA + ks * 32;
                uint32_t rh[4], rl[4];
                ldmx4(rh, kb + 2 * QTILE_B + off);
                ldmx4(rl, kb + 3 * QTILE_B + off);
                mma_bf16(o[2 * np],     phf[ks], &rh[0]);
                mma_bf16(o[2 * np],     phf[ks], &rl[0]);
                mma_bf16(o[2 * np],     plf[ks], &rh[0]);
                mma_bf16(o[2 * np + 1], phf[ks], &rh[2]);
                mma_bf16(o[2 * np + 1], phf[ks], &rl[2]);
                mma_bf16(o[2 * np + 1], plf[ks], &rh[2]);
            }

        __syncthreads();
        if (kt + 2 < nt) prefetch(kt + 2, s);
    }

    // ---- epilogue: y = o / l, write bf16 hi/lo ----
    const int b = bh / NHEAD, h = bh % NHEAD;
    const float inv0 = 1.f / l0, inv1 = 1.f / l1;
    const int t_0 = q0 + wm * 16 + r0;
#pragma unroll
    for (int ni = 0; ni < 8; ni++) {
        const int d = ni * 8 + 2 * (lane & 3);
#pragma unroll
        for (int half = 0; half < 2; half++) {
            const int t = t_0 + half * 8;
            const float inv = half ? inv1 : inv0;
            float a0 = o[ni][2 * half + 0] * inv;
            float a1 = o[ni][2 * half + 1] * inv;
            __nv_bfloat16 h0 = __float2bfloat16(a0);
            __nv_bfloat16 h1 = __float2bfloat16(a1);
            size_t idx = ((size_t)b * SEQ + t) * CDIM + h * HDIM + d;
            *(uint32_t*)(g_yh + idx) = ((uint32_t)*(uint16_t*)&h1 << 16) |
                                       (uint32_t)*(uint16_t*)&h0;
            *(uint32_t*)(g_yl + idx) = packbf(a0 - __bfloat162float(h0),
                                              a1 - __bfloat162float(h1));
        }
    }
}

// ---------------------------------------------------------------------------
extern "C" void kernel_launch(void* const* d_in, const int* in_sizes, int n_in,
                              void* d_out, int out_size)
{
    const float* x  = (const float*)d_in[0];
    const float* Wa = (const float*)d_in[1];
    const float* ba = (const float*)d_in[2];
    const float* Wp = (const float*)d_in[3];
    const float* bp = (const float*)d_in[4];
    float* out = (float*)d_out;

    cudaFuncSetAttribute(attn_kernel,
                         cudaFuncAttributeMaxDynamicSharedMemorySize, ATTN_SMEM);
    cudaFuncSetAttribute(tc_gemm<1>,
                         cudaFuncAttributeMaxDynamicSharedMemorySize, GEMM_SMEM);
    cudaFuncSetAttribute(tc_gemm<0>,
                         cudaFuncAttributeMaxDynamicSharedMemorySize, GEMM_SMEM);

    const int nx = MTOT * CDIM;

    // 1) bf16 hi/lo splits of x and the (transposed) weights
    split_x<<<nx / 1024, 256>>>(x, nx);
    tsplit_kernel<0><<<dim3(N_QKV / 32, CDIM / 32), dim3(32, 8)>>>(Wa, CDIM, N_QKV);
    tsplit_kernel<1><<<dim3(CDIM / 32, CDIM / 32), dim3(32, 8)>>>(Wp, CDIM, CDIM);

    // 2) QKV projection -> bf16 hi/lo q/k ([bh,t,d]) + transposed v ([bh,d,t])
    tc_gemm<1><<<dim3(N_QKV / 128, MTOT / 128), 256, GEMM_SMEM>>>(ba, nullptr);

    // 3) Causal flash attention on HMMA -> yh/yl bf16
    attn_kernel<<<dim3(NBH, SEQ / 64), 128, ATTN_SMEM>>>();

    // 4) Output projection
    tc_gemm<0><<<dim3(CDIM / 128, MTOT / 128), 256, GEMM_SMEM>>>(bp, out);
}

// round 15
// speedup vs baseline: 3.0620x; 1.0211x over previous
#include <cuda_runtime.h>
#include <cuda_bf16.h>
#include <cstdint>
#include <math.h>

// Problem constants
#define BATCH 8
#define SEQ   1024
#define CDIM  768
#define NHEAD 12
#define HDIM  64
#define MTOT  (BATCH * SEQ)      // 8192
#define N_QKV (3 * CDIM)         // 2304
#define NBH   (BATCH * NHEAD)    // 96

// ---------------------------------------------------------------------------
// Scratch (allocation-free rule: __device__ globals)
// ---------------------------------------------------------------------------
__device__ __nv_bfloat16 g_xh[MTOT * CDIM];
__device__ __nv_bfloat16 g_xl[MTOT * CDIM];
__device__ __nv_bfloat16 g_yh[MTOT * CDIM];
__device__ __nv_bfloat16 g_yl[MTOT * CDIM];
__device__ __nv_bfloat16 g_wah[N_QKV * CDIM];   // W_attn^T  [N=2304, K=768]
__device__ __nv_bfloat16 g_wal[N_QKV * CDIM];
__device__ __nv_bfloat16 g_wph[CDIM * CDIM];    // W_proj^T  [N=768,  K=768]
__device__ __nv_bfloat16 g_wpl[CDIM * CDIM];
// attention operands, bf16 hi/lo, per-head layouts
__device__ __nv_bfloat16 g_qh[NBH * SEQ * HDIM];   // [bh][t][d] (q pre-scaled)
__device__ __nv_bfloat16 g_ql[NBH * SEQ * HDIM];
__device__ __nv_bfloat16 g_kh[NBH * SEQ * HDIM];   // [bh][t][d]
__device__ __nv_bfloat16 g_kl[NBH * SEQ * HDIM];
__device__ __nv_bfloat16 g_vh[NBH * HDIM * SEQ];   // [bh][d][t]  (transposed)
__device__ __nv_bfloat16 g_vl[NBH * HDIM * SEQ];

// ---------------------------------------------------------------------------
// PTX helpers (arch-agnostic: valid on compute_103 / sm_103)
// ---------------------------------------------------------------------------
__device__ __forceinline__ uint32_t smem_u32(const void* p) {
    uint32_t a;
    asm("{ .reg .u64 t; cvta.to.shared.u64 t, %1; cvt.u32.u64 %0, t; }"
        : "=r"(a) : "l"(p));
    return a;
}

__device__ __forceinline__ void cp16(uint32_t saddr, const void* g) {
    asm volatile("cp.async.cg.shared.global [%0], [%1], 16;"
                 :: "r"(saddr), "l"(g) : "memory");
}

__device__ __forceinline__ void ldmx4(uint32_t* r, uint32_t addr) {
    asm volatile("ldmatrix.sync.aligned.m8n8.x4.shared.b16 {%0,%1,%2,%3}, [%4];"
                 : "=r"(r[0]), "=r"(r[1]), "=r"(r[2]), "=r"(r[3]) : "r"(addr));
}

__device__ __forceinline__ void mma_bf16(float* d, const uint32_t* a,
                                         const uint32_t* b) {
    asm volatile(
        "mma.sync.aligned.m16n8k16.row.col.f32.bf16.bf16.f32 "
        "{%0,%1,%2,%3}, {%4,%5,%6,%7}, {%8,%9}, {%0,%1,%2,%3};"
        : "+f"(d[0]), "+f"(d[1]), "+f"(d[2]), "+f"(d[3])
        : "r"(a[0]), "r"(a[1]), "r"(a[2]), "r"(a[3]), "r"(b[0]), "r"(b[1]));
}

__device__ __forceinline__ uint32_t packbf(float a, float b) {
    __nv_bfloat162 t = __floats2bfloat162_rn(a, b);
    return *(uint32_t*)&t;
}

// ---------------------------------------------------------------------------
// bf16 hi/lo split of x
// ---------------------------------------------------------------------------
__global__ void split_x(const float* __restrict__ in, int n) {
    int idx = (blockIdx.x * blockDim.x + threadIdx.x) * 4;
    if (idx >= n) return;
    float4 v = *(const float4*)(in + idx);
    __nv_bfloat16 h0 = __float2bfloat16(v.x);
    __nv_bfloat16 h1 = __float2bfloat16(v.y);
    __nv_bfloat16 h2 = __float2bfloat16(v.z);
    __nv_bfloat16 h3 = __float2bfloat16(v.w);
    __nv_bfloat16 l0 = __float2bfloat16(v.x - __bfloat162float(h0));
    __nv_bfloat16 l1 = __float2bfloat16(v.y - __bfloat162float(h1));
    __nv_bfloat16 l2 = __float2bfloat16(v.z - __bfloat162float(h2));
    __nv_bfloat16 l3 = __float2bfloat16(v.w - __bfloat162float(h3));
    __nv_bfloat162 a, b;
    a.x = h0; a.y = h1; b.x = h2; b.y = h3;
    *(__nv_bfloat162*)(g_xh + idx)     = a;
    *(__nv_bfloat162*)(g_xh + idx + 2) = b;
    a.x = l0; a.y = l1; b.x = l2; b.y = l3;
    *(__nv_bfloat162*)(g_xl + idx)     = a;
    *(__nv_bfloat162*)(g_xl + idx + 2) = b;
}

// Transpose + split: in [R, C] fp32 -> hi/lo [C, R] bf16
template <int WHICH>
__global__ void tsplit_kernel(const float* __restrict__ in, int R, int C) {
    __nv_bfloat16* hi = WHICH ? g_wph : g_wah;
    __nv_bfloat16* lo = WHICH ? g_wpl : g_wal;
    __shared__ float tile[32][33];
    int c0 = blockIdx.x * 32, r0 = blockIdx.y * 32;
    int tx = threadIdx.x, ty = threadIdx.y;
#pragma unroll
    for (int dy = 0; dy < 32; dy += 8)
        tile[ty + dy][tx] = in[(r0 + ty + dy) * C + c0 + tx];
    __syncthreads();
#pragma unroll
    for (int dy = 0; dy < 32; dy += 8) {
        int c = c0 + ty + dy, r = r0 + tx;
        float v = tile[tx][ty + dy];
        __nv_bfloat16 h = __float2bfloat16(v);
        __nv_bfloat16 l = __float2bfloat16(v - __bfloat162float(h));
        hi[(size_t)c * R + r] = h;
        lo[(size_t)c * R + r] = l;
    }
}

// ---------------------------------------------------------------------------
// HMMA GEMM (unchanged from R12 WIN): 128x128 tile, BK=32, 2-stage cp.async,
// __launch_bounds__(256,2) pins regs<=128 -> 2 CTA/SM.
// ---------------------------------------------------------------------------
#define BK        32
#define ROWB      80
#define TILE_B    (128 * ROWB)
#define STAGE_B   (4 * TILE_B)
#define GEMM_SMEM (2 * STAGE_B)
#define VP        136

template <int MODE>
__global__ __launch_bounds__(256, 2)
void tc_gemm(const float* __restrict__ bias, float* __restrict__ Cout) {
    constexpr int N = MODE ? N_QKV : CDIM;
    constexpr int K = CDIM;
    constexpr int NCH = K / BK;

    const __nv_bfloat16* Ah = MODE ? g_xh : g_yh;
    const __nv_bfloat16* Al = MODE ? g_xl : g_yl;
    const __nv_bfloat16* Bh = MODE ? g_wah : g_wph;
    const __nv_bfloat16* Bl = MODE ? g_wal : g_wpl;

    extern __shared__ char smem[];
    const uint32_t sb = smem_u32(smem);

    const int tid  = threadIdx.x;
    const int lane = tid & 31;
    const int w    = tid >> 5;
    const int wm   = w & 3;
    const int wn   = w >> 2;
    const int m0   = blockIdx.y * 128;
    const int n0   = blockIdx.x * 128;

    float acc[2][8][4];
#pragma unroll
    for (int i = 0; i < 2; i++)
#pragma unroll
        for (int j = 0; j < 8; j++)
#pragma unroll
            for (int v = 0; v < 4; v++) acc[i][j][v] = 0.f;

    auto prefetch = [&](int c, int s) {
        const int k0 = c * BK;
        const uint32_t stage = sb + (uint32_t)s * STAGE_B;
#pragma unroll
        for (int t = 0; t < 8; t++) {
            int idx  = tid + t * 256;
            int tile = idx >> 9;
            int wi   = idx & 511;
            int r    = wi >> 2;
            int ch   = wi & 3;
            uint32_t saddr = stage + (uint32_t)tile * TILE_B + r * ROWB + ch * 16;
            const __nv_bfloat16* src;
            if (tile == 0)      src = Ah + (size_t)(m0 + r) * K + k0 + ch * 8;
            else if (tile == 1) src = Al + (size_t)(m0 + r) * K + k0 + ch * 8;
            else if (tile == 2) src = Bh + (size_t)(n0 + r) * K + k0 + ch * 8;
            else                src = Bl + (size_t)(n0 + r) * K + k0 + ch * 8;
            cp16(saddr, src);
        }
        asm volatile("cp.async.commit_group;" ::: "memory");
    };

    prefetch(0, 0);
    prefetch(1, 1);

    const uint32_t a_off =
        (uint32_t)(wm * 32 + (lane & 15)) * ROWB + ((lane >> 4) << 3) * 2;
    const uint32_t b_off =
        (uint32_t)(wn * 64 + (lane & 7) + ((lane >> 4) << 3)) * ROWB +
        (((lane >> 3) & 1) << 3) * 2;

    for (int c = 0; c < NCH; c++) {
        const int s = c & 1;
        if (c + 1 < NCH)
            asm volatile("cp.async.wait_group 1;" ::: "memory");
        else
            asm volatile("cp.async.wait_group 0;" ::: "memory");
        __syncthreads();

        const uint32_t stage = sb + (uint32_t)s * STAGE_B;
#pragma unroll
        for (int kk = 0; kk < BK; kk += 16) {
            uint32_t ah[2][4], al[2][4], bh[8][2], bl[8][2];
#pragma unroll
            for (int mi = 0; mi < 2; mi++) {
                uint32_t off = a_off + (uint32_t)(mi * 16) * ROWB + kk * 2;
                ldmx4(ah[mi], stage + off);
                ldmx4(al[mi], stage + TILE_B + off);
            }
#pragma unroll
            for (int np = 0; np < 4; np++) {
                uint32_t off = b_off + (uint32_t)(np * 16) * ROWB + kk * 2;
                uint32_t rh[4], rl[4];
                ldmx4(rh, stage + 2 * TILE_B + off);
                ldmx4(rl, stage + 3 * TILE_B + off);
                bh[2 * np][0] = rh[0]; bh[2 * np][1] = rh[1];
                bh[2 * np + 1][0] = rh[2]; bh[2 * np + 1][1] = rh[3];
                bl[2 * np][0] = rl[0]; bl[2 * np][1] = rl[1];
                bl[2 * np + 1][0] = rl[2]; bl[2 * np + 1][1] = rl[3];
            }
#pragma unroll
            for (int mi = 0; mi < 2; mi++)
#pragma unroll
                for (int ni = 0; ni < 8; ni++) {
                    mma_bf16(acc[mi][ni], ah[mi], bh[ni]);
                    mma_bf16(acc[mi][ni], ah[mi], bl[ni]);
                    mma_bf16(acc[mi][ni], al[mi], bh[ni]);
                }
        }
        __syncthreads();
        if (c + 2 < NCH) prefetch(c + 2, s);
    }

    // ---- epilogue ----
    const int mrow = m0 + wm * 32 + (lane >> 2);
    const int ncol = n0 + wn * 64 + 2 * (lane & 3);

    if (MODE == 0) {
#pragma unroll
        for (int mi = 0; mi < 2; mi++)
#pragma unroll
            for (int ni = 0; ni < 8; ni++) {
                const int n = ncol + ni * 8;
                const float b0 = bias[n], b1 = bias[n + 1];
#pragma unroll
                for (int half = 0; half < 2; half++) {
                    const int m = mrow + mi * 16 + half * 8;
                    float2 o;
                    o.x = acc[mi][ni][2 * half + 0] + b0;
                    o.y = acc[mi][ni][2 * half + 1] + b1;
                    *(float2*)(Cout + (size_t)m * N + n) = o;
                }
            }
        return;
    }

    const int which = n0 / CDIM;
    const int bb = m0 >> 10;
    const int t0 = m0 & 1023;

    if (which < 2) {
        __nv_bfloat16* dh = which == 0 ? g_qh : g_kh;
        __nv_bfloat16* dl = which == 0 ? g_ql : g_kl;
        const float scl = (which == 0) ? 0.125f : 1.0f;
#pragma unroll
        for (int mi = 0; mi < 2; mi++)
#pragma unroll
            for (int ni = 0; ni < 8; ni++) {
                const int n = ncol + ni * 8;
                const float b0 = bias[n], b1 = bias[n + 1];
                const int cloc = n - which * CDIM;
                const int h = cloc >> 6, d = cloc & 63;
#pragma unroll
                for (int half = 0; half < 2; half++) {
                    const int m = mrow + mi * 16 + half * 8;
                    const int t = m & 1023;
                    float a0 = (acc[mi][ni][2 * half + 0] + b0) * scl;
                    float a1 = (acc[mi][ni][2 * half + 1] + b1) * scl;
                    __nv_bfloat16 h0 = __float2bfloat16(a0);
                    __nv_bfloat16 h1 = __float2bfloat16(a1);
                    size_t idx = (((size_t)((m >> 10) * NHEAD + h) * SEQ + t)
                                  * HDIM + d);
                    *(uint32_t*)(dh + idx) = ((uint32_t)*(uint16_t*)&h1 << 16) |
                                             (uint32_t)*(uint16_t*)&h0;
                    *(uint32_t*)(dl + idx) =
                        packbf(a0 - __bfloat162float(h0),
                               a1 - __bfloat162float(h1));
                }
            }
    } else {
        __nv_bfloat16* svh = (__nv_bfloat16*)smem;
        __nv_bfloat16* svl = svh + 128 * VP;
        const int vch0 = n0 - 2 * CDIM;
#pragma unroll
        for (int mi = 0; mi < 2; mi++)
#pragma unroll
            for (int ni = 0; ni < 8; ni++) {
                const int n = ncol + ni * 8;
                const float b0 = bias[n], b1 = bias[n + 1];
                const int cl = n - n0;
#pragma unroll
                for (int half = 0; half < 2; half++) {
                    const int ml = (mrow - m0) + mi * 16 + half * 8;
                    float a0 = acc[mi][ni][2 * half + 0] + b0;
                    float a1 = acc[mi][ni][2 * half + 1] + b1;
                    __nv_bfloat16 h0 = __float2bfloat16(a0);
                    __nv_bfloat16 h1 = __float2bfloat16(a1);
                    svh[cl * VP + ml]       = h0;
                    svh[(cl + 1) * VP + ml] = h1;
                    svl[cl * VP + ml]       =
                        __float2bfloat16(a0 - __bfloat162float(h0));
                    svl[(cl + 1) * VP + ml] =
                        __float2bfloat16(a1 - __bfloat162float(h1));
                }
            }
        __syncthreads();
#pragma unroll
        for (int t = 0; t < 16; t++) {
            int idx = tid + t * 256;
            int arr = idx >> 11;
            int wi  = idx & 2047;
            int r   = wi >> 4;
            int ch  = wi & 15;
            const __nv_bfloat16* s = (arr ? svl : svh) + r * VP + ch * 8;
            uint4 val = *(const uint4*)s;
            const int gc = vch0 + r;
            const int h = gc >> 6, d = gc & 63;
            __nv_bfloat16* dst = (arr ? g_vl : g_vh) +
                (((size_t)(bb * NHEAD + h) * HDIM + d) * SEQ + t0 + ch * 8);
            *(uint4*)dst = val;
        }
    }
}

// ---------------------------------------------------------------------------
// Flash attention on HMMA, widened CTA: 128 q-rows x 8 warps (16 rows each),
// 256 threads, KV tile 64. smem 110592 -> 2 CTA/SM = 16 warps (25% occ, was
// 12.5%). nt = 2*qt+2; elementwise causal mask on the last TWO kv tiles
// (the 128x128 diagonal block spans two 64-wide tiles).
// ---------------------------------------------------------------------------
#define ROWA      144                          // 64 bf16 = 128B + 16B pad
#define QTILE_B   (128 * ROWA)                 // 18432 B (128 q rows)
#define KTILE_B   (64 * ROWA)                  // 9216 B  (64 kv rows)
#define ASTAGE_B  (4 * KTILE_B)                // kh,kl,vh,vl = 36864 B
#define ATTN_SMEM (2 * QTILE_B + 2 * ASTAGE_B) // 110592 B

__global__ __launch_bounds__(256, 2)
void attn_kernel()
{
    extern __shared__ char smem[];
    const uint32_t sb = smem_u32(smem);

    const int bh = blockIdx.x;                 // 0..95
    const int qt = blockIdx.y;                 // 0..7
    const int q0 = qt * 128;
    const int tid  = threadIdx.x;
    const int lane = tid & 31;
    const int wm   = tid >> 5;                 // warp 0..7 -> q rows wm*16..+16
    const int nt   = 2 * qt + 2;               // causal kv tiles (>=2)

    // ---- stage Q (hi+lo): 2 tiles x 128 rows x 8 chunks = 2048 ----
#pragma unroll
    for (int t = 0; t < 8; t++) {
        int idx = tid + t * 256;               // 0..2047
        int tile = idx >> 10;                  // 0=hi 1=lo
        int wi = idx & 1023;
        int r = wi >> 3, ch = wi & 7;          // r 0..127
        const __nv_bfloat16* src = (tile ? g_ql : g_qh) +
            ((size_t)bh * SEQ + q0 + r) * HDIM + ch * 8;
        cp16(sb + tile * QTILE_B + r * ROWA + ch * 16, src);
    }
    asm volatile("cp.async.commit_group;" ::: "memory");

    auto prefetch = [&](int c, int s) {
        const int kv0 = c * 64;
        const uint32_t stage = sb + 2 * QTILE_B + (uint32_t)s * ASTAGE_B;
#pragma unroll
        for (int t = 0; t < 8; t++) {
            int idx = tid + t * 256;           // 0..2047
            int tile = idx >> 9;               // 0=kh 1=kl 2=vh 3=vl
            int wi = idx & 511;
            int r = wi >> 3, ch = wi & 7;      // r 0..63
            const __nv_bfloat16* src;
            if (tile == 0)
                src = g_kh + ((size_t)bh * SEQ + kv0 + r) * HDIM + ch * 8;
            else if (tile == 1)
                src = g_kl + ((size_t)bh * SEQ + kv0 + r) * HDIM + ch * 8;
            else if (tile == 2)
                src = g_vh + ((size_t)bh * HDIM + r) * SEQ + kv0 + ch * 8;
            else
                src = g_vl + ((size_t)bh * HDIM + r) * SEQ + kv0 + ch * 8;
            cp16(stage + (uint32_t)tile * KTILE_B + r * ROWA + ch * 16, src);
        }
        asm volatile("cp.async.commit_group;" ::: "memory");
    };

    prefetch(0, 0);
    prefetch(1, 1);                            // nt >= 2 always

    // Q ready (<=2 pending -> Q group retired)
    asm volatile("cp.async.wait_group 2;" ::: "memory");
    __syncthreads();

    const uint32_t a_off =
        (uint32_t)(lane & 15) * ROWA + ((lane >> 4) << 3) * 2;
    const uint32_t b_off =
        (uint32_t)((lane & 7) + ((lane >> 4) << 3)) * ROWA +
        (((lane >> 3) & 1) << 3) * 2;

    uint32_t qhf[4][4], qlf[4][4];
#pragma unroll
    for (int ks = 0; ks < 4; ks++) {
        uint32_t off = (uint32_t)(wm * 16) * ROWA + a_off + ks * 32;
        ldmx4(qhf[ks], sb + off);
        ldmx4(qlf[ks], sb + QTILE_B + off);
    }

    float o[8][4];
#pragma unroll
    for (int i = 0; i < 8; i++)
#pragma unroll
        for (int j = 0; j < 4; j++) o[i][j] = 0.f;
    float m0 = -1e30f, m1 = -1e30f, l0 = 0.f, l1 = 0.f;

    const int r0 = lane >> 2;                  // local row within warp tile

    for (int kt = 0; kt < nt; kt++) {
        const int s = kt & 1;
        if (kt + 1 < nt)
            asm volatile("cp.async.wait_group 1;" ::: "memory");
        else
            asm volatile("cp.async.wait_group 0;" ::: "memory");
        __syncthreads();

        const uint32_t kb = sb + 2 * QTILE_B + (uint32_t)s * ASTAGE_B;
        const int kv0 = kt * 64;

        // ---- S = Q @ K^T (hi/lo 3-product) ----
        float s_[8][4];
#pragma unroll
        for (int i = 0; i < 8; i++)
#pragma unroll
            for (int j = 0; j < 4; j++) s_[i][j] = 0.f;

#pragma unroll
        for (int np = 0; np < 4; np++)
#pragma unroll
            for (int ks = 0; ks < 4; ks++) {
                uint32_t off = b_off + (uint32_t)(np * 16) * ROWA + ks * 32;
                uint32_t rh[4], rl[4];
                ldmx4(rh, kb + off);
                ldmx4(rl, kb + KTILE_B + off);
                mma_bf16(s_[2 * np],     qhf[ks], &rh[0]);
                mma_bf16(s_[2 * np],     qhf[ks], &rl[0]);
                mma_bf16(s_[2 * np],     qlf[ks], &rh[0]);
                mma_bf16(s_[2 * np + 1], qhf[ks], &rh[2]);
                mma_bf16(s_[2 * np + 1], qhf[ks], &rl[2]);
                mma_bf16(s_[2 * np + 1], qlf[ks], &rh[2]);
            }

        // ---- causal mask (diagonal block spans the last two kv tiles) ----
        if (kt >= nt - 2) {
            const int grow0 = q0 + wm * 16 + r0;
#pragma unroll
            for (int ni = 0; ni < 8; ni++) {
                const int col = kv0 + ni * 8 + 2 * (lane & 3);
                if (col > grow0)     s_[ni][0] = -1e30f;
                if (col + 1 > grow0) s_[ni][1] = -1e30f;
                if (col > grow0 + 8)     s_[ni][2] = -1e30f;
                if (col + 1 > grow0 + 8) s_[ni][3] = -1e30f;
            }
        }

        // ---- online softmax (rows r0, r0+8; quad = lanes sharing row) ----
        float mx0 = -1e30f, mx1 = -1e30f;
#pragma unroll
        for (int ni = 0; ni < 8; ni++) {
            mx0 = fmaxf(mx0, fmaxf(s_[ni][0], s_[ni][1]));
            mx1 = fmaxf(mx1, fmaxf(s_[ni][2], s_[ni][3]));
        }
        mx0 = fmaxf(mx0, __shfl_xor_sync(0xffffffffu, mx0, 1));
        mx0 = fmaxf(mx0, __shfl_xor_sync(0xffffffffu, mx0, 2));
        mx1 = fmaxf(mx1, __shfl_xor_sync(0xffffffffu, mx1, 1));
        mx1 = fmaxf(mx1, __shfl_xor_sync(0xffffffffu, mx1, 2));
        const float mn0 = fmaxf(m0, mx0), mn1 = fmaxf(m1, mx1);
        const float al0 = __expf(m0 - mn0), al1 = __expf(m1 - mn1);
        float rs0 = 0.f, rs1 = 0.f;
#pragma unroll
        for (int ni = 0; ni < 8; ni++) {
            s_[ni][0] = __expf(s_[ni][0] - mn0);
            s_[ni][1] = __expf(s_[ni][1] - mn0);
            s_[ni][2] = __expf(s_[ni][2] - mn1);
            s_[ni][3] = __expf(s_[ni][3] - mn1);
            rs0 += s_[ni][0] + s_[ni][1];
            rs1 += s_[ni][2] + s_[ni][3];
        }
        rs0 += __shfl_xor_sync(0xffffffffu, rs0, 1);
        rs0 += __shfl_xor_sync(0xffffffffu, rs0, 2);
        rs1 += __shfl_xor_sync(0xffffffffu, rs1, 1);
        rs1 += __shfl_xor_sync(0xffffffffu, rs1, 2);
        l0 = l0 * al0 + rs0; l1 = l1 * al1 + rs1;
        m0 = mn0; m1 = mn1;
#pragma unroll
        for (int ni = 0; ni < 8; ni++) {
            o[ni][0] *= al0; o[ni][1] *= al0;
            o[ni][2] *= al1; o[ni][3] *= al1;
        }

        // ---- P fragments (hi/lo) ----
        uint32_t phf[4][4], plf[4][4];
#pragma unroll
        for (int j = 0; j < 4; j++)
#pragma unroll
            for (int half = 0; half < 2; half++) {
                const float* sv = s_[2 * j + half];
                __nv_bfloat16 h0 = __float2bfloat16(sv[0]);
                __nv_bfloat16 h1 = __float2bfloat16(sv[1]);
                __nv_bfloat16 h2 = __float2bfloat16(sv[2]);
                __nv_bfloat16 h3 = __float2bfloat16(sv[3]);
                phf[j][2 * half]     = ((uint32_t)*(uint16_t*)&h1 << 16) |
                                       (uint32_t)*(uint16_t*)&h0;
                phf[j][2 * half + 1] = ((uint32_t)*(uint16_t*)&h3 << 16) |
                                       (uint32_t)*(uint16_t*)&h2;
                plf[j][2 * half] = packbf(sv[0] - __bfloat162float(h0),
                                          sv[1] - __bfloat162float(h1));
                plf[j][2 * half + 1] = packbf(sv[2] - __bfloat162float(h2),
                                              sv[3] - __bfloat162float(h3));
            }

        // ---- O += P @ V (hi/lo 3-product); V^T tile rows=d, cols=kv ----
#pragma unroll
        for (int np = 0; np < 4; np++)
#pragma unroll
            for (int ks = 0; ks < 4; ks++) {
                uint32_t off = b_off + (uint32_t)(np * 16) * ROWA + ks * 32;
                uint32_t rh[4], rl[4];
                ldmx4(rh, kb + 2 * KTILE_B + off);
                ldmx4(rl, kb + 3 * KTILE_B + off);
                mma_bf16(o[2 * np],     phf[ks], &rh[0]);
                mma_bf16(o[2 * np],     phf[ks], &rl[0]);
                mma_bf16(o[2 * np],     plf[ks], &rh[0]);
                mma_bf16(o[2 * np + 1], phf[ks], &rh[2]);
                mma_bf16(o[2 * np + 1], phf[ks], &rl[2]);
                mma_bf16(o[2 * np + 1], plf[ks], &rh[2]);
            }

        __syncthreads();
        if (kt + 2 < nt) prefetch(kt + 2, s);
    }

    // ---- epilogue: y = o / l, write bf16 hi/lo ----
    const int b = bh / NHEAD, h = bh % NHEAD;
    const float inv0 = 1.f / l0, inv1 = 1.f / l1;
    const int t_0 = q0 + wm * 16 + r0;
#pragma unroll
    for (int ni = 0; ni < 8; ni++) {
        const int d = ni * 8 + 2 * (lane & 3);
#pragma unroll
        for (int half = 0; half < 2; half++) {
            const int t = t_0 + half * 8;
            const float inv = half ? inv1 : inv0;
            float a0 = o[ni][2 * half + 0] * inv;
            float a1 = o[ni][2 * half + 1] * inv;
            __nv_bfloat16 h0 = __float2bfloat16(a0);
            __nv_bfloat16 h1 = __float2bfloat16(a1);
            size_t idx = ((size_t)b * SEQ + t) * CDIM + h * HDIM + d;
            *(uint32_t*)(g_yh + idx) = ((uint32_t)*(uint16_t*)&h1 << 16) |
                                       (uint32_t)*(uint16_t*)&h0;
            *(uint32_t*)(g_yl + idx) = packbf(a0 - __bfloat162float(h0),
                                              a1 - __bfloat162float(h1));
        }
    }
}

// ---------------------------------------------------------------------------
extern "C" void kernel_launch(void* const* d_in, const int* in_sizes, int n_in,
                              void* d_out, int out_size)
{
    const float* x  = (const float*)d_in[0];
    const float* Wa = (const float*)d_in[1];
    const float* ba = (const float*)d_in[2];
    const float* Wp = (const float*)d_in[3];
    const float* bp = (const float*)d_in[4];
    float* out = (float*)d_out;

    cudaFuncSetAttribute(attn_kernel,
                         cudaFuncAttributeMaxDynamicSharedMemorySize, ATTN_SMEM);
    cudaFuncSetAttribute(tc_gemm<1>,
                         cudaFuncAttributeMaxDynamicSharedMemorySize, GEMM_SMEM);
    cudaFuncSetAttribute(tc_gemm<0>,
                         cudaFuncAttributeMaxDynamicSharedMemorySize, GEMM_SMEM);

    const int nx = MTOT * CDIM;

    // 1) bf16 hi/lo splits of x and the (transposed) weights
    split_x<<<nx / 1024, 256>>>(x, nx);
    tsplit_kernel<0><<<dim3(N_QKV / 32, CDIM / 32), dim3(32, 8)>>>(Wa, CDIM, N_QKV);
    tsplit_kernel<1><<<dim3(CDIM / 32, CDIM / 32), dim3(32, 8)>>>(Wp, CDIM, CDIM);

    // 2) QKV projection -> bf16 hi/lo q/k ([bh,t,d]) + transposed v ([bh,d,t])
    tc_gemm<1><<<dim3(N_QKV / 128, MTOT / 128), 256, GEMM_SMEM>>>(ba, nullptr);

    // 3) Causal flash attention on HMMA (128-q-row CTAs) -> yh/yl bf16
    attn_kernel<<<dim3(NBH, SEQ / 128), 256, ATTN_SMEM>>>();

    // 4) Output projection
    tc_gemm<0><<<dim3(CDIM / 128, MTOT / 128), 256, GEMM_SMEM>>>(bp, out);
}